// round 10
// baseline (speedup 1.0000x reference)
#include <cuda_runtime.h>
#include <cuda_fp16.h>
#include <cstdint>

#define BATCHES 16
#define NPTS    1024
#define DIMS    1024
#define EPS_SK  1e-3f
#define INT8_IT   16
#define POLISH_IT  3

// ---------------- scratch (static device globals; no runtime alloc) --------
__device__ __half         d_C [BATCHES * NPTS * NPTS];   // fp16 C (polish, 32 MB)
__device__ unsigned char  d_C8[BATCHES * NPTS * NPTS];   // uint8 C = rn(255*C/2) (16 MB)
__device__ __half  d_xh[BATCHES * NPTS * DIMS];
__device__ __half  d_yh[BATCHES * NPTS * DIMS];
__device__ float   d_vpart[BATCHES * 8 * NPTS];          // per-rank column partials
__device__ unsigned d_maxbits;
__device__ unsigned d_bar[BATCHES * 32];                 // per-batch barrier ctrs

// ---------------- normalize rows -> fp16 (+ fused per-replay init) ----------
__global__ void normc_kernel(const float* __restrict__ x,
                             const float* __restrict__ y,
                             float* __restrict__ out) {
    if (blockIdx.x == 0) {
        for (int t = threadIdx.x; t < BATCHES * 32; t += blockDim.x) d_bar[t] = 0u;
        if (threadIdx.x == 0) { d_maxbits = 0u; out[0] = 0.0f; }
    }
    int gw   = blockIdx.x * 8 + (threadIdx.x >> 5);
    int lane = threadIdx.x & 31;
    const float* src;
    __half* dst;
    if (gw < BATCHES * NPTS) { src = x + (size_t)gw * DIMS;                     dst = d_xh + (size_t)gw * DIMS; }
    else                     { src = y + (size_t)(gw - BATCHES * NPTS) * DIMS;  dst = d_yh + (size_t)(gw - BATCHES * NPTS) * DIMS; }
    const float4* p = (const float4*)src;
    float4 f[8];
    float ss = 0.0f;
#pragma unroll
    for (int k = 0; k < 8; k++) {
        f[k] = p[lane + 32 * k];
        ss += f[k].x * f[k].x + f[k].y * f[k].y + f[k].z * f[k].z + f[k].w * f[k].w;
    }
#pragma unroll
    for (int o = 16; o; o >>= 1) ss += __shfl_xor_sync(0xffffffffu, ss, o);
    float inv = 1.0f / fmaxf(sqrtf(ss), 1e-12f);
#pragma unroll
    for (int k = 0; k < 8; k++) {
        __half2 h0 = __floats2half2_rn(f[k].x * inv, f[k].y * inv);
        __half2 h1 = __floats2half2_rn(f[k].z * inv, f[k].w * inv);
        uint2 u; u.x = *(unsigned*)&h0; u.y = *(unsigned*)&h1;
        *(uint2*)(dst + (size_t)(lane + 32 * k) * 4) = u;
    }
}

// ---------------- tensor-core cost GEMM ------------------------------------
#define SSTRIDE 40
#define CTSTR   136

#define CP_ASYNC16(saddr, gptr) \
    asm volatile("cp.async.cg.shared.global [%0], [%1], 16;" :: "r"(saddr), "l"(gptr))
#define CP_COMMIT() asm volatile("cp.async.commit_group;")
#define CP_WAIT0()  asm volatile("cp.async.wait_group 0;" ::: "memory")

#define LDSM_X4(r0, r1, r2, r3, addr)                                          \
    asm volatile("ldmatrix.sync.aligned.m8n8.x4.shared.b16 {%0,%1,%2,%3}, [%4];" \
        : "=r"(r0), "=r"(r1), "=r"(r2), "=r"(r3) : "r"(addr))
#define LDSM_X2(r0, r1, addr)                                                  \
    asm volatile("ldmatrix.sync.aligned.m8n8.x2.shared.b16 {%0,%1}, [%2];"     \
        : "=r"(r0), "=r"(r1) : "r"(addr))

__device__ __forceinline__ void mma16816(float* d, const unsigned* a, const unsigned* b) {
    asm volatile(
        "mma.sync.aligned.m16n8k16.row.col.f32.f16.f16.f32 "
        "{%0,%1,%2,%3}, {%4,%5,%6,%7}, {%8,%9}, {%0,%1,%2,%3};"
        : "+f"(d[0]), "+f"(d[1]), "+f"(d[2]), "+f"(d[3])
        : "r"(a[0]), "r"(a[1]), "r"(a[2]), "r"(a[3]), "r"(b[0]), "r"(b[1]));
}

__device__ __forceinline__ unsigned char q8(__half h) {
    return (unsigned char)__float2uint_rn(__saturatef(__half2float(h) * 0.5f) * 255.0f);
}

__global__ void __launch_bounds__(256, 2)
gemm_cost_mma(void) {
    __shared__ __align__(16) __half smem_all[4 * 128 * SSTRIDE];  // A0,A1,B0,B1
    __shared__ float s_wmax[8];

    const int tid  = threadIdx.x;
    const int warp = tid >> 5;
    const int lane = tid & 31;
    const int wm   = warp >> 2;
    const int wn   = warp & 3;
    const int lq   = lane >> 2;
    const int lr4  = lane & 3;
    const int bz   = blockIdx.z;
    const int n0   = blockIdx.y * 128;
    const int m0   = blockIdx.x * 128;

    const __half* xb = d_xh + ((size_t)bz << 20);
    const __half* yb = d_yh + ((size_t)bz << 20);

    const int lrow = tid >> 2;
    const int lseg = tid & 3;
    const __half* gxa = xb + (size_t)(n0 + lrow) * DIMS + lseg * 8;
    const __half* gxb = xb + (size_t)(n0 + lrow + 64) * DIMS + lseg * 8;
    const __half* gya = yb + (size_t)(m0 + lrow) * DIMS + lseg * 8;
    const __half* gyb = yb + (size_t)(m0 + lrow + 64) * DIMS + lseg * 8;

    const uint32_t smem_u32 = (uint32_t)__cvta_generic_to_shared(smem_all);
    const uint32_t STG = (uint32_t)(128 * SSTRIDE * 2);
    const uint32_t sAa = smem_u32 + 2u * (lrow * SSTRIDE + lseg * 8);
    const uint32_t sAb = smem_u32 + 2u * ((lrow + 64) * SSTRIDE + lseg * 8);
    const uint32_t sBa = smem_u32 + 2u * STG + 2u * (lrow * SSTRIDE + lseg * 8);
    const uint32_t sBb = smem_u32 + 2u * STG + 2u * ((lrow + 64) * SSTRIDE + lseg * 8);

#define LOAD_STAGE(stg, k0)                                   \
    { CP_ASYNC16(sAa + (stg) * STG, gxa + (k0));              \
      CP_ASYNC16(sAb + (stg) * STG, gxb + (k0));              \
      CP_ASYNC16(sBa + (stg) * STG, gya + (k0));              \
      CP_ASYNC16(sBb + (stg) * STG, gyb + (k0)); }

    const int arow_l = (lane & 7) + ((lane >> 3) & 1) * 8;
    const int acol_l = (lane >> 4) * 8;
    const int brow_l = lane & 7;
    const int bcol_l = ((lane >> 3) & 1) * 8;

    float acc[4][4][4];
#pragma unroll
    for (int i = 0; i < 4; i++)
#pragma unroll
        for (int j = 0; j < 4; j++)
#pragma unroll
            for (int q = 0; q < 4; q++) acc[i][j][q] = 0.0f;

    LOAD_STAGE(0u, 0);
    CP_COMMIT();

    for (int it = 0; it < 32; it++) {
        CP_WAIT0();
        __syncthreads();
        if (it < 31) {
            LOAD_STAGE((uint32_t)((it + 1) & 1), (it + 1) * 32);
            CP_COMMIT();
        }
        const uint32_t aS = smem_u32 + (uint32_t)(it & 1) * STG;
        const uint32_t bS = smem_u32 + 2u * STG + (uint32_t)(it & 1) * STG;
#pragma unroll
        for (int ks = 0; ks < 32; ks += 16) {
            unsigned a[4][4], b[4][2];
#pragma unroll
            for (int i = 0; i < 4; i++) {
                uint32_t ad = aS + 2u * ((wm * 64 + i * 16 + arow_l) * SSTRIDE + ks + acol_l);
                LDSM_X4(a[i][0], a[i][1], a[i][2], a[i][3], ad);
            }
#pragma unroll
            for (int j = 0; j < 4; j++) {
                uint32_t bd = bS + 2u * ((wn * 32 + j * 8 + brow_l) * SSTRIDE + ks + bcol_l);
                LDSM_X2(b[j][0], b[j][1], bd);
            }
#pragma unroll
            for (int i = 0; i < 4; i++)
#pragma unroll
                for (int j = 0; j < 4; j++) mma16816(acc[i][j], a[i], b[j]);
        }
    }
    __syncthreads();
#undef LOAD_STAGE

    // epilogue: cost = 1 - dot; stage fp16 tile, write C fp16 + C8 uint8
    __half* Ct = smem_all;
    float mx = 0.0f;
#pragma unroll
    for (int i = 0; i < 4; i++) {
        const int r0 = wm * 64 + i * 16 + lq;
#pragma unroll
        for (int j = 0; j < 4; j++) {
            const int c = wn * 32 + j * 8 + lr4 * 2;
            float c00 = 1.0f - acc[i][j][0];
            float c01 = 1.0f - acc[i][j][1];
            float c10 = 1.0f - acc[i][j][2];
            float c11 = 1.0f - acc[i][j][3];
            mx = fmaxf(mx, fmaxf(fmaxf(c00, c01), fmaxf(c10, c11)));
            *(__half2*)(Ct + r0 * CTSTR + c)       = __floats2half2_rn(c00, c01);
            *(__half2*)(Ct + (r0 + 8) * CTSTR + c) = __floats2half2_rn(c10, c11);
        }
    }
    __syncthreads();

    const size_t base = (size_t)bz << 20;
    const int row = tid >> 1;
    const int off = (tid & 1) * 64;
    {   // C fp16 rows
#pragma unroll
        for (int u = 0; u < 8; u++) {
            uint4 q = *(const uint4*)(Ct + row * CTSTR + off + u * 8);
            *(uint4*)(d_C + base + (size_t)(n0 + row) * NPTS + m0 + off + u * 8) = q;
        }
    }
    {   // C8 uint8 rows
#pragma unroll
        for (int u = 0; u < 4; u++) {
            const __half* s = Ct + row * CTSTR + off + u * 16;
            uint4 q;
            unsigned w[4];
#pragma unroll
            for (int p = 0; p < 4; p++) {
                w[p] = (unsigned)q8(s[4 * p]) | ((unsigned)q8(s[4 * p + 1]) << 8) |
                       ((unsigned)q8(s[4 * p + 2]) << 16) | ((unsigned)q8(s[4 * p + 3]) << 24);
            }
            q.x = w[0]; q.y = w[1]; q.z = w[2]; q.w = w[3];
            *(uint4*)(d_C8 + base + (size_t)(n0 + row) * NPTS + m0 + off + u * 16) = q;
        }
    }

#pragma unroll
    for (int o = 16; o; o >>= 1) mx = fmaxf(mx, __shfl_xor_sync(0xffffffffu, mx, o));
    if (lane == 0) s_wmax[warp] = mx;
    __syncthreads();
    if (tid == 0) {
        float bm = s_wmax[0];
#pragma unroll
        for (int w = 1; w < 8; w++) bm = fmaxf(bm, s_wmax[w]);
        atomicMax(&d_maxbits, __float_as_uint(bm));
    }
}

// ---------------- persistent Sinkhorn: one barrier/iter, no C^T -------------
#define SK_GRID 128
#define SK_DSMEM 170768

__device__ __forceinline__ void batch_barrier(int batch, unsigned target) {
    __syncthreads();
    if (threadIdx.x == 0) {
        __threadfence();
        unsigned* ctr = &d_bar[batch * 32];
        atomicAdd(ctr, 1u);
        while (*((volatile unsigned*)ctr) < target) { }
        __threadfence();
    }
    __syncthreads();
}

__device__ __forceinline__ __half2 h2u(unsigned u) { return *(__half2*)&u; }

// uint8 row dot (row as 2 uint4 per lane-chunk) vs v chunks
__device__ __forceinline__ float dotrow_q(uint4 q0, uint4 q1,
                                          const uint4 va0, const uint4 va1,
                                          const uint4 vb0, const uint4 vb1) {
    const unsigned K = 0x64006400u;
    const __half2 k = *(const __half2*)&K;
    __half2 A = __floats2half2_rn(0.f, 0.f);
    __half2 B = A;
#define QW(w, v01, v23)                                                        \
    { unsigned rlo, rhi;                                                       \
      asm("prmt.b32 %0,%1,%2,0x5140;" : "=r"(rlo) : "r"(w), "r"(0x64646464u)); \
      asm("prmt.b32 %0,%1,%2,0x7362;" : "=r"(rhi) : "r"(w), "r"(0x64646464u)); \
      A = __hfma2(__hsub2(*(__half2*)&rlo, k), *(const __half2*)&(v01), A);    \
      B = __hfma2(__hsub2(*(__half2*)&rhi, k), *(const __half2*)&(v23), B); }
    QW(q0.x, va0.x, va0.y) QW(q0.y, va0.z, va0.w)
    QW(q0.z, va1.x, va1.y) QW(q0.w, va1.z, va1.w)
    QW(q1.x, vb0.x, vb0.y) QW(q1.y, vb0.z, vb0.w)
    QW(q1.z, vb1.x, vb1.y) QW(q1.w, vb1.z, vb1.w)
#undef QW
    return __low2float(A) + __high2float(A) + __low2float(B) + __high2float(B);
}

// 4 row dots from the padded smem slab (stride 65 uint4)
__device__ __forceinline__ void dot4q_s(const uint4* __restrict__ sw,
                                        const uint4* __restrict__ sv4, int lane,
                                        float& s0, float& s1, float& s2, float& s3) {
    const uint4 va0 = sv4[2 * lane], va1 = sv4[2 * lane + 1];
    const uint4 vb0 = sv4[64 + 2 * lane], vb1 = sv4[64 + 2 * lane + 1];
    s0 = dotrow_q(sw[lane],       sw[32 + lane],  va0, va1, vb0, vb1);
    s1 = dotrow_q(sw[65 + lane],  sw[97 + lane],  va0, va1, vb0, vb1);
    s2 = dotrow_q(sw[130 + lane], sw[162 + lane], va0, va1, vb0, vb1);
    s3 = dotrow_q(sw[195 + lane], sw[227 + lane], va0, va1, vb0, vb1);
}

// fp16 4-row dot from global C
__device__ __forceinline__ void dot4h(const __half* __restrict__ rowbase,
                                      const __half2* __restrict__ sv2, int lane,
                                      float& s0, float& s1, float& s2, float& s3) {
    const uint4* r = (const uint4*)rowbase;
    __half2 z = __floats2half2_rn(0.f, 0.f);
    __half2 a0a = z, a0b = z, a1a = z, a1b = z, a2a = z, a2b = z, a3a = z, a3b = z;
#pragma unroll
    for (int k = 0; k < 4; k++) {
        int idx = lane + 32 * k;
        uint4 vv = *(const uint4*)(sv2 + idx * 4);
        __half2 v0 = h2u(vv.x), v1 = h2u(vv.y), v2 = h2u(vv.z), v3 = h2u(vv.w);
        uint4 q0 = r[idx];
        uint4 q1 = r[idx + 128];
        uint4 q2 = r[idx + 256];
        uint4 q3 = r[idx + 384];
        a0a = __hfma2(h2u(q0.x), v0, a0a); a0b = __hfma2(h2u(q0.y), v1, a0b);
        a0a = __hfma2(h2u(q0.z), v2, a0a); a0b = __hfma2(h2u(q0.w), v3, a0b);
        a1a = __hfma2(h2u(q1.x), v0, a1a); a1b = __hfma2(h2u(q1.y), v1, a1b);
        a1a = __hfma2(h2u(q1.z), v2, a1a); a1b = __hfma2(h2u(q1.w), v3, a1b);
        a2a = __hfma2(h2u(q2.x), v0, a2a); a2b = __hfma2(h2u(q2.y), v1, a2b);
        a2a = __hfma2(h2u(q2.z), v2, a2a); a2b = __hfma2(h2u(q2.w), v3, a2b);
        a3a = __hfma2(h2u(q3.x), v0, a3a); a3b = __hfma2(h2u(q3.y), v1, a3b);
        a3a = __hfma2(h2u(q3.z), v2, a3a); a3b = __hfma2(h2u(q3.w), v3, a3b);
    }
    s0 = __low2float(a0a) + __high2float(a0a) + __low2float(a0b) + __high2float(a0b);
    s1 = __low2float(a1a) + __high2float(a1a) + __low2float(a1b) + __high2float(a1b);
    s2 = __low2float(a2a) + __high2float(a2a) + __low2float(a2b) + __high2float(a2b);
    s3 = __low2float(a3a) + __high2float(a3a) + __low2float(a3b) + __high2float(a3b);
}

#define WARP_RED4(s0, s1, s2, s3)                          \
    _Pragma("unroll")                                      \
    for (int o = 16; o; o >>= 1) {                         \
        s0 += __shfl_xor_sync(0xffffffffu, s0, o);         \
        s1 += __shfl_xor_sync(0xffffffffu, s1, o);         \
        s2 += __shfl_xor_sync(0xffffffffu, s2, o);         \
        s3 += __shfl_xor_sync(0xffffffffu, s3, o);         \
    }

// decode one uint (4 uint8 cols) and accumulate into 2 half2 col-accumulators
#define CDEC(w, aE, aO, u2, kb)                                                \
    { unsigned rlo, rhi;                                                       \
      asm("prmt.b32 %0,%1,%2,0x5140;" : "=r"(rlo) : "r"(w), "r"(0x64646464u)); \
      asm("prmt.b32 %0,%1,%2,0x7362;" : "=r"(rhi) : "r"(w), "r"(0x64646464u)); \
      aE = __hfma2(__hsub2(*(__half2*)&rlo, kb), u2, aE);                      \
      aO = __hfma2(__hsub2(*(__half2*)&rhi, kb), u2, aO); }

__global__ void __launch_bounds__(1024, 1)
sinkhorn_kernel(float* __restrict__ out) {
    extern __shared__ __align__(16) unsigned char sk[];
    uint4*   slab = (uint4*)sk;
    __half*  sv   = (__half*)(sk + 133120);
    __half*  suh  = (__half*)(sk + 135168);
    __half2* sred = (__half2*)(sk + 135936);
    float*   saux = (float*)(sk + 170752);

    const int tid   = threadIdx.x;
    const int warp  = tid >> 5;
    const int lane  = tid & 31;
    const int blk   = blockIdx.x;
    const int batch = blk >> 3;
    const int rank  = blk & 7;
    const int cg    = tid >> 4;     // column group (16 cols)
    const int rc    = tid & 15;     // row chunk

    // preload uint8 slab (128 rows, padded to 65 uint4 stride)
    {
        const uint4* src = (const uint4*)(d_C8 + ((size_t)batch << 20) + ((size_t)rank << 17));
#pragma unroll
        for (int j = 0; j < 8; j++) {
            int g = tid + 1024 * j;
            slab[(g >> 6) * 65 + (g & 63)] = src[g];
        }
    }
    sv[tid] = __float2half(1.0f / NPTS);
    if (tid == 0) saux[0] = 0.0f;

    const float invM = 1.0f / __uint_as_float(d_maxbits);
    const float qsc  = invM * (2.0f / 255.0f);
    float* vp_mine = d_vpart + (batch * 8 + rank) * NPTS;
    const float* vp_all = d_vpart + batch * 8 * NPTS;
    const unsigned KB = 0x64006400u;
    const __half2 kb = *(const __half2*)&KB;
    __syncthreads();

    unsigned step = 0;
    for (int iter = 0; iter < INT8_IT; iter++) {
        // ---- u (local rows, smem slab)
        float s0, s1, s2, s3;
        dot4q_s(slab + warp * 4 * 65, (const uint4*)sv, lane, s0, s1, s2, s3);
        WARP_RED4(s0, s1, s2, s3)
        if (lane < 4) {
            float s = (lane == 0) ? s0 : (lane == 1) ? s1 : (lane == 2) ? s2 : s3;
            float uv = 1.0f / (fmaf(qsc, s, EPS_SK));
            suh[warp * 4 + lane] = __float2half(uv);
        }
        __syncthreads();

        // ---- column partials from own slab (rows rc+16j, bank-safe)
        {
            __half2 z = __floats2half2_rn(0.f, 0.f);
            __half2 acc[8] = {z, z, z, z, z, z, z, z};
#pragma unroll
            for (int j = 0; j < 8; j++) {
                int r = rc + 16 * j;
                uint4 q = slab[r * 65 + cg];
                __half2 u2 = __half2half2(suh[r]);
                CDEC(q.x, acc[0], acc[1], u2, kb)
                CDEC(q.y, acc[2], acc[3], u2, kb)
                CDEC(q.z, acc[4], acc[5], u2, kb)
                CDEC(q.w, acc[6], acc[7], u2, kb)
            }
#pragma unroll
            for (int h = 0; h < 8; h++) sred[(cg * 8 + h) * 17 + rc] = acc[h];
        }
        __syncthreads();
        if (tid < 512) {
            const __half2* p = sred + tid * 17;
            float fx = 0.f, fy = 0.f;
#pragma unroll
            for (int k2 = 0; k2 < 16; k2++) {
                float2 f = __half22float2(p[k2]);
                fx += f.x; fy += f.y;
            }
            int m0 = 16 * (tid >> 3) + 2 * (tid & 7);
            float2 st; st.x = fx; st.y = fy;
            *(float2*)(vp_mine + m0) = st;
        }
        batch_barrier(batch, 8 * (++step));
        // ---- v recompute (identical in all blocks of the batch)
        {
            float a = 0.f;
#pragma unroll
            for (int k = 0; k < 8; k++) a += vp_all[k * NPTS + tid];
            sv[tid] = __float2half(1.0f / (fmaf(qsc, a, EPS_SK)));
        }
        __syncthreads();
    }

    // ---- polish iterations: same structure on fp16 C from global
    const __half* Cb = d_C + ((size_t)batch << 20) + ((size_t)rank << 17);
    float last_a = 0.0f;   // this thread's final column-sum (C^T u)_tid
    for (int iter = 0; iter < POLISH_IT; iter++) {
        float s0, s1, s2, s3;
        dot4h(Cb + (size_t)(warp * 4) * NPTS, (const __half2*)sv, lane, s0, s1, s2, s3);
        WARP_RED4(s0, s1, s2, s3)
        if (lane < 4) {
            float s = (lane == 0) ? s0 : (lane == 1) ? s1 : (lane == 2) ? s2 : s3;
            float uv = 1.0f / (fmaf(invM, s, EPS_SK));
            suh[warp * 4 + lane] = __float2half(uv);
        }
        __syncthreads();
        {
            __half2 z = __floats2half2_rn(0.f, 0.f);
            __half2 acc[8] = {z, z, z, z, z, z, z, z};
#pragma unroll
            for (int j = 0; j < 8; j++) {
                int r = rc + 16 * j;
                const uint4* gq = (const uint4*)(Cb + (size_t)r * NPTS) + 2 * cg;
                uint4 q0 = gq[0], q1 = gq[1];
                __half2 u2 = __half2half2(suh[r]);
                acc[0] = __hfma2(h2u(q0.x), u2, acc[0]);
                acc[1] = __hfma2(h2u(q0.y), u2, acc[1]);
                acc[2] = __hfma2(h2u(q0.z), u2, acc[2]);
                acc[3] = __hfma2(h2u(q0.w), u2, acc[3]);
                acc[4] = __hfma2(h2u(q1.x), u2, acc[4]);
                acc[5] = __hfma2(h2u(q1.y), u2, acc[5]);
                acc[6] = __hfma2(h2u(q1.z), u2, acc[6]);
                acc[7] = __hfma2(h2u(q1.w), u2, acc[7]);
            }
#pragma unroll
            for (int h = 0; h < 8; h++) sred[(cg * 8 + h) * 17 + rc] = acc[h];
        }
        __syncthreads();
        if (tid < 512) {
            const __half2* p = sred + tid * 17;
            float fx = 0.f, fy = 0.f;
#pragma unroll
            for (int k2 = 0; k2 < 16; k2++) {
                float2 f = __half22float2(p[k2]);
                fx += f.x; fy += f.y;
            }
            int m0 = 16 * (tid >> 3) + 2 * (tid & 7);
            float2 st; st.x = fx; st.y = fy;
            *(float2*)(vp_mine + m0) = st;
        }
        batch_barrier(batch, 8 * (++step));
        {
            float a = 0.f;
#pragma unroll
            for (int k = 0; k < 8; k++) a += vp_all[k * NPTS + tid];
            last_a = a;
            sv[tid] = __float2half(1.0f / (fmaf(invM, a, EPS_SK)));
        }
        __syncthreads();
    }

    // ---- distance = invM * Σ_j a_j v_j  (a_j = (C^T u)_j from last polish,
    //      v_j = 1/(invM a_j + eps)) — algebraically equal to u·C·v, no extra
    //      matvec. Every block holds the FULL column set; rank 0 commits.
    {
        float v  = 1.0f / (fmaf(invM, last_a, EPS_SK));
        float c  = invM * last_a * v;
#pragma unroll
        for (int o = 16; o; o >>= 1) c += __shfl_xor_sync(0xffffffffu, c, o);
        if (lane == 0) atomicAdd(&saux[0], c);
        __syncthreads();
        if (tid == 0 && rank == 0) atomicAdd(out, saux[0] * (1.0f / BATCHES));
    }
}

// ---------------- launch ----------------------------------------------------
extern "C" void kernel_launch(void* const* d_in, const int* in_sizes, int n_in,
                              void* d_out, int out_size) {
    (void)in_sizes; (void)n_in; (void)out_size;
    const float* x = (const float*)d_in[0];
    const float* y = (const float*)d_in[1];
    float* out = (float*)d_out;

    static int attr_set = 0;
    if (!attr_set) {
        cudaFuncSetAttribute(sinkhorn_kernel,
                             cudaFuncAttributeMaxDynamicSharedMemorySize, SK_DSMEM);
        attr_set = 1;
    }

    normc_kernel<<<4096, 256>>>(x, y, out);
    dim3 g(8, 8, 16);
    gemm_cost_mma<<<g, 256>>>();
    sinkhorn_kernel<<<SK_GRID, 1024, SK_DSMEM>>>(out);
}

// round 11
// speedup vs baseline: 1.5782x; 1.5782x over previous
#include <cuda_runtime.h>
#include <cuda_fp16.h>
#include <cstdint>

#define BATCHES 16
#define NPTS    1024
#define DIMS    1024
#define EPS_SK  1e-3f
#define INT8_IT   14
#define POLISH_IT  3

// ---------------- scratch (static device globals; no runtime alloc) --------
__device__ __half         d_C [BATCHES * NPTS * NPTS];   // fp16 C (polish, 32 MB)
__device__ unsigned char  d_C8[BATCHES * NPTS * NPTS];   // uint8 C = rn(255*C/2) (16 MB)
__device__ __half  d_xh[BATCHES * NPTS * DIMS];
__device__ __half  d_yh[BATCHES * NPTS * DIMS];
__device__ float   d_vpart[BATCHES * 8 * NPTS];          // per-rank column partials
__device__ unsigned d_maxbits;
__device__ unsigned d_bar[BATCHES * 32];                 // per-batch barrier ctrs

// ---------------- normalize rows -> fp16 (+ fused per-replay init) ----------
__global__ void normc_kernel(const float* __restrict__ x,
                             const float* __restrict__ y,
                             float* __restrict__ out) {
    if (blockIdx.x == 0) {
        for (int t = threadIdx.x; t < BATCHES * 32; t += blockDim.x) d_bar[t] = 0u;
        if (threadIdx.x == 0) { d_maxbits = 0u; out[0] = 0.0f; }
    }
    int gw   = blockIdx.x * 8 + (threadIdx.x >> 5);
    int lane = threadIdx.x & 31;
    const float* src;
    __half* dst;
    if (gw < BATCHES * NPTS) { src = x + (size_t)gw * DIMS;                     dst = d_xh + (size_t)gw * DIMS; }
    else                     { src = y + (size_t)(gw - BATCHES * NPTS) * DIMS;  dst = d_yh + (size_t)(gw - BATCHES * NPTS) * DIMS; }
    const float4* p = (const float4*)src;
    float4 f[8];
    float ss = 0.0f;
#pragma unroll
    for (int k = 0; k < 8; k++) {
        f[k] = p[lane + 32 * k];
        ss += f[k].x * f[k].x + f[k].y * f[k].y + f[k].z * f[k].z + f[k].w * f[k].w;
    }
#pragma unroll
    for (int o = 16; o; o >>= 1) ss += __shfl_xor_sync(0xffffffffu, ss, o);
    float inv = 1.0f / fmaxf(sqrtf(ss), 1e-12f);
#pragma unroll
    for (int k = 0; k < 8; k++) {
        __half2 h0 = __floats2half2_rn(f[k].x * inv, f[k].y * inv);
        __half2 h1 = __floats2half2_rn(f[k].z * inv, f[k].w * inv);
        uint2 u; u.x = *(unsigned*)&h0; u.y = *(unsigned*)&h1;
        *(uint2*)(dst + (size_t)(lane + 32 * k) * 4) = u;
    }
}

// ---------------- tensor-core cost GEMM ------------------------------------
#define SSTRIDE 40
#define CTSTR   136

#define CP_ASYNC16(saddr, gptr) \
    asm volatile("cp.async.cg.shared.global [%0], [%1], 16;" :: "r"(saddr), "l"(gptr))
#define CP_COMMIT() asm volatile("cp.async.commit_group;")
#define CP_WAIT0()  asm volatile("cp.async.wait_group 0;" ::: "memory")

#define LDSM_X4(r0, r1, r2, r3, addr)                                          \
    asm volatile("ldmatrix.sync.aligned.m8n8.x4.shared.b16 {%0,%1,%2,%3}, [%4];" \
        : "=r"(r0), "=r"(r1), "=r"(r2), "=r"(r3) : "r"(addr))
#define LDSM_X2(r0, r1, addr)                                                  \
    asm volatile("ldmatrix.sync.aligned.m8n8.x2.shared.b16 {%0,%1}, [%2];"     \
        : "=r"(r0), "=r"(r1) : "r"(addr))

__device__ __forceinline__ void mma16816(float* d, const unsigned* a, const unsigned* b) {
    asm volatile(
        "mma.sync.aligned.m16n8k16.row.col.f32.f16.f16.f32 "
        "{%0,%1,%2,%3}, {%4,%5,%6,%7}, {%8,%9}, {%0,%1,%2,%3};"
        : "+f"(d[0]), "+f"(d[1]), "+f"(d[2]), "+f"(d[3])
        : "r"(a[0]), "r"(a[1]), "r"(a[2]), "r"(a[3]), "r"(b[0]), "r"(b[1]));
}

__device__ __forceinline__ unsigned char q8(__half h) {
    return (unsigned char)__float2uint_rn(__saturatef(__half2float(h) * 0.5f) * 255.0f);
}

__global__ void __launch_bounds__(256, 2)
gemm_cost_mma(void) {
    __shared__ __align__(16) __half smem_all[4 * 128 * SSTRIDE];  // A0,A1,B0,B1
    __shared__ float s_wmax[8];

    const int tid  = threadIdx.x;
    const int warp = tid >> 5;
    const int lane = tid & 31;
    const int wm   = warp >> 2;
    const int wn   = warp & 3;
    const int lq   = lane >> 2;
    const int lr4  = lane & 3;
    const int bz   = blockIdx.z;
    const int n0   = blockIdx.y * 128;
    const int m0   = blockIdx.x * 128;

    const __half* xb = d_xh + ((size_t)bz << 20);
    const __half* yb = d_yh + ((size_t)bz << 20);

    const int lrow = tid >> 2;
    const int lseg = tid & 3;
    const __half* gxa = xb + (size_t)(n0 + lrow) * DIMS + lseg * 8;
    const __half* gxb = xb + (size_t)(n0 + lrow + 64) * DIMS + lseg * 8;
    const __half* gya = yb + (size_t)(m0 + lrow) * DIMS + lseg * 8;
    const __half* gyb = yb + (size_t)(m0 + lrow + 64) * DIMS + lseg * 8;

    const uint32_t smem_u32 = (uint32_t)__cvta_generic_to_shared(smem_all);
    const uint32_t STG = (uint32_t)(128 * SSTRIDE * 2);
    const uint32_t sAa = smem_u32 + 2u * (lrow * SSTRIDE + lseg * 8);
    const uint32_t sAb = smem_u32 + 2u * ((lrow + 64) * SSTRIDE + lseg * 8);
    const uint32_t sBa = smem_u32 + 2u * STG + 2u * (lrow * SSTRIDE + lseg * 8);
    const uint32_t sBb = smem_u32 + 2u * STG + 2u * ((lrow + 64) * SSTRIDE + lseg * 8);

#define LOAD_STAGE(stg, k0)                                   \
    { CP_ASYNC16(sAa + (stg) * STG, gxa + (k0));              \
      CP_ASYNC16(sAb + (stg) * STG, gxb + (k0));              \
      CP_ASYNC16(sBa + (stg) * STG, gya + (k0));              \
      CP_ASYNC16(sBb + (stg) * STG, gyb + (k0)); }

    const int arow_l = (lane & 7) + ((lane >> 3) & 1) * 8;
    const int acol_l = (lane >> 4) * 8;
    const int brow_l = lane & 7;
    const int bcol_l = ((lane >> 3) & 1) * 8;

    float acc[4][4][4];
#pragma unroll
    for (int i = 0; i < 4; i++)
#pragma unroll
        for (int j = 0; j < 4; j++)
#pragma unroll
            for (int q = 0; q < 4; q++) acc[i][j][q] = 0.0f;

    LOAD_STAGE(0u, 0);
    CP_COMMIT();

    for (int it = 0; it < 32; it++) {
        CP_WAIT0();
        __syncthreads();
        if (it < 31) {
            LOAD_STAGE((uint32_t)((it + 1) & 1), (it + 1) * 32);
            CP_COMMIT();
        }
        const uint32_t aS = smem_u32 + (uint32_t)(it & 1) * STG;
        const uint32_t bS = smem_u32 + 2u * STG + (uint32_t)(it & 1) * STG;
#pragma unroll
        for (int ks = 0; ks < 32; ks += 16) {
            unsigned a[4][4], b[4][2];
#pragma unroll
            for (int i = 0; i < 4; i++) {
                uint32_t ad = aS + 2u * ((wm * 64 + i * 16 + arow_l) * SSTRIDE + ks + acol_l);
                LDSM_X4(a[i][0], a[i][1], a[i][2], a[i][3], ad);
            }
#pragma unroll
            for (int j = 0; j < 4; j++) {
                uint32_t bd = bS + 2u * ((wn * 32 + j * 8 + brow_l) * SSTRIDE + ks + bcol_l);
                LDSM_X2(b[j][0], b[j][1], bd);
            }
#pragma unroll
            for (int i = 0; i < 4; i++)
#pragma unroll
                for (int j = 0; j < 4; j++) mma16816(acc[i][j], a[i], b[j]);
        }
    }
    __syncthreads();
#undef LOAD_STAGE

    // epilogue: cost = 1 - dot; stage fp16 tile, write C fp16 + C8 uint8
    __half* Ct = smem_all;
    float mx = 0.0f;
#pragma unroll
    for (int i = 0; i < 4; i++) {
        const int r0 = wm * 64 + i * 16 + lq;
#pragma unroll
        for (int j = 0; j < 4; j++) {
            const int c = wn * 32 + j * 8 + lr4 * 2;
            float c00 = 1.0f - acc[i][j][0];
            float c01 = 1.0f - acc[i][j][1];
            float c10 = 1.0f - acc[i][j][2];
            float c11 = 1.0f - acc[i][j][3];
            mx = fmaxf(mx, fmaxf(fmaxf(c00, c01), fmaxf(c10, c11)));
            *(__half2*)(Ct + r0 * CTSTR + c)       = __floats2half2_rn(c00, c01);
            *(__half2*)(Ct + (r0 + 8) * CTSTR + c) = __floats2half2_rn(c10, c11);
        }
    }
    __syncthreads();

    const size_t base = (size_t)bz << 20;
    const int row = tid >> 1;
    const int off = (tid & 1) * 64;
    {   // C fp16 rows
#pragma unroll
        for (int u = 0; u < 8; u++) {
            uint4 q = *(const uint4*)(Ct + row * CTSTR + off + u * 8);
            *(uint4*)(d_C + base + (size_t)(n0 + row) * NPTS + m0 + off + u * 8) = q;
        }
    }
    {   // C8 uint8 rows
#pragma unroll
        for (int u = 0; u < 4; u++) {
            const __half* s = Ct + row * CTSTR + off + u * 16;
            uint4 q;
            unsigned w[4];
#pragma unroll
            for (int p = 0; p < 4; p++) {
                w[p] = (unsigned)q8(s[4 * p]) | ((unsigned)q8(s[4 * p + 1]) << 8) |
                       ((unsigned)q8(s[4 * p + 2]) << 16) | ((unsigned)q8(s[4 * p + 3]) << 24);
            }
            q.x = w[0]; q.y = w[1]; q.z = w[2]; q.w = w[3];
            *(uint4*)(d_C8 + base + (size_t)(n0 + row) * NPTS + m0 + off + u * 16) = q;
        }
    }

#pragma unroll
    for (int o = 16; o; o >>= 1) mx = fmaxf(mx, __shfl_xor_sync(0xffffffffu, mx, o));
    if (lane == 0) s_wmax[warp] = mx;
    __syncthreads();
    if (tid == 0) {
        float bm = s_wmax[0];
#pragma unroll
        for (int w = 1; w < 8; w++) bm = fmaxf(bm, s_wmax[w]);
        atomicMax(&d_maxbits, __float_as_uint(bm));
    }
}

// ---------------- persistent Sinkhorn: one barrier/iter, no C^T -------------
#define SK_GRID 128
#define SK_DSMEM 170768

// release/acquire barrier (cooperative-groups grid-sync pattern):
// __syncthreads orders the block's writes before thread 0's release-add;
// acquire-poll makes remote writes visible before the trailing __syncthreads.
__device__ __forceinline__ void batch_barrier(int batch, unsigned target) {
    __syncthreads();
    if (threadIdx.x == 0) {
        unsigned* ctr = &d_bar[batch * 32];
        asm volatile("red.release.gpu.global.add.u32 [%0], %1;"
                     :: "l"(ctr), "r"(1u) : "memory");
        unsigned v;
        do {
            asm volatile("ld.acquire.gpu.global.u32 %0, [%1];"
                         : "=r"(v) : "l"(ctr) : "memory");
        } while (v < target);
    }
    __syncthreads();
}

__device__ __forceinline__ __half2 h2u(unsigned u) { return *(__half2*)&u; }

// uint8 row dot (row as 2 uint4 per lane-chunk) vs v chunks
__device__ __forceinline__ float dotrow_q(uint4 q0, uint4 q1,
                                          const uint4 va0, const uint4 va1,
                                          const uint4 vb0, const uint4 vb1) {
    const unsigned K = 0x64006400u;
    const __half2 k = *(const __half2*)&K;
    __half2 A = __floats2half2_rn(0.f, 0.f);
    __half2 B = A;
#define QW(w, v01, v23)                                                        \
    { unsigned rlo, rhi;                                                       \
      asm("prmt.b32 %0,%1,%2,0x5140;" : "=r"(rlo) : "r"(w), "r"(0x64646464u)); \
      asm("prmt.b32 %0,%1,%2,0x7362;" : "=r"(rhi) : "r"(w), "r"(0x64646464u)); \
      A = __hfma2(__hsub2(*(__half2*)&rlo, k), *(const __half2*)&(v01), A);    \
      B = __hfma2(__hsub2(*(__half2*)&rhi, k), *(const __half2*)&(v23), B); }
    QW(q0.x, va0.x, va0.y) QW(q0.y, va0.z, va0.w)
    QW(q0.z, va1.x, va1.y) QW(q0.w, va1.z, va1.w)
    QW(q1.x, vb0.x, vb0.y) QW(q1.y, vb0.z, vb0.w)
    QW(q1.z, vb1.x, vb1.y) QW(q1.w, vb1.z, vb1.w)
#undef QW
    return __low2float(A) + __high2float(A) + __low2float(B) + __high2float(B);
}

// 4 row dots from the padded smem slab (stride 65 uint4)
__device__ __forceinline__ void dot4q_s(const uint4* __restrict__ sw,
                                        const uint4* __restrict__ sv4, int lane,
                                        float& s0, float& s1, float& s2, float& s3) {
    const uint4 va0 = sv4[2 * lane], va1 = sv4[2 * lane + 1];
    const uint4 vb0 = sv4[64 + 2 * lane], vb1 = sv4[64 + 2 * lane + 1];
    s0 = dotrow_q(sw[lane],       sw[32 + lane],  va0, va1, vb0, vb1);
    s1 = dotrow_q(sw[65 + lane],  sw[97 + lane],  va0, va1, vb0, vb1);
    s2 = dotrow_q(sw[130 + lane], sw[162 + lane], va0, va1, vb0, vb1);
    s3 = dotrow_q(sw[195 + lane], sw[227 + lane], va0, va1, vb0, vb1);
}

// fp16 4-row dot from global C
__device__ __forceinline__ void dot4h(const __half* __restrict__ rowbase,
                                      const __half2* __restrict__ sv2, int lane,
                                      float& s0, float& s1, float& s2, float& s3) {
    const uint4* r = (const uint4*)rowbase;
    __half2 z = __floats2half2_rn(0.f, 0.f);
    __half2 a0a = z, a0b = z, a1a = z, a1b = z, a2a = z, a2b = z, a3a = z, a3b = z;
#pragma unroll
    for (int k = 0; k < 4; k++) {
        int idx = lane + 32 * k;
        uint4 vv = *(const uint4*)(sv2 + idx * 4);
        __half2 v0 = h2u(vv.x), v1 = h2u(vv.y), v2 = h2u(vv.z), v3 = h2u(vv.w);
        uint4 q0 = r[idx];
        uint4 q1 = r[idx + 128];
        uint4 q2 = r[idx + 256];
        uint4 q3 = r[idx + 384];
        a0a = __hfma2(h2u(q0.x), v0, a0a); a0b = __hfma2(h2u(q0.y), v1, a0b);
        a0a = __hfma2(h2u(q0.z), v2, a0a); a0b = __hfma2(h2u(q0.w), v3, a0b);
        a1a = __hfma2(h2u(q1.x), v0, a1a); a1b = __hfma2(h2u(q1.y), v1, a1b);
        a1a = __hfma2(h2u(q1.z), v2, a1a); a1b = __hfma2(h2u(q1.w), v3, a1b);
        a2a = __hfma2(h2u(q2.x), v0, a2a); a2b = __hfma2(h2u(q2.y), v1, a2b);
        a2a = __hfma2(h2u(q2.z), v2, a2a); a2b = __hfma2(h2u(q2.w), v3, a2b);
        a3a = __hfma2(h2u(q3.x), v0, a3a); a3b = __hfma2(h2u(q3.y), v1, a3b);
        a3a = __hfma2(h2u(q3.z), v2, a3a); a3b = __hfma2(h2u(q3.w), v3, a3b);
    }
    s0 = __low2float(a0a) + __high2float(a0a) + __low2float(a0b) + __high2float(a0b);
    s1 = __low2float(a1a) + __high2float(a1a) + __low2float(a1b) + __high2float(a1b);
    s2 = __low2float(a2a) + __high2float(a2a) + __low2float(a2b) + __high2float(a2b);
    s3 = __low2float(a3a) + __high2float(a3a) + __low2float(a3b) + __high2float(a3b);
}

#define WARP_RED4(s0, s1, s2, s3)                          \
    _Pragma("unroll")                                      \
    for (int o = 16; o; o >>= 1) {                         \
        s0 += __shfl_xor_sync(0xffffffffu, s0, o);         \
        s1 += __shfl_xor_sync(0xffffffffu, s1, o);         \
        s2 += __shfl_xor_sync(0xffffffffu, s2, o);         \
        s3 += __shfl_xor_sync(0xffffffffu, s3, o);         \
    }

// decode one uint (4 uint8 cols) and accumulate into 2 half2 col-accumulators
#define CDEC(w, aE, aO, u2, kb)                                                \
    { unsigned rlo, rhi;                                                       \
      asm("prmt.b32 %0,%1,%2,0x5140;" : "=r"(rlo) : "r"(w), "r"(0x64646464u)); \
      asm("prmt.b32 %0,%1,%2,0x7362;" : "=r"(rhi) : "r"(w), "r"(0x64646464u)); \
      aE = __hfma2(__hsub2(*(__half2*)&rlo, kb), u2, aE);                      \
      aO = __hfma2(__hsub2(*(__half2*)&rhi, kb), u2, aO); }

__global__ void __launch_bounds__(1024, 1)
sinkhorn_kernel(float* __restrict__ out) {
    extern __shared__ __align__(16) unsigned char sk[];
    uint4*   slab = (uint4*)sk;
    __half*  sv   = (__half*)(sk + 133120);
    __half*  suh  = (__half*)(sk + 135168);
    __half2* sred = (__half2*)(sk + 135936);
    float*   saux = (float*)(sk + 170752);

    const int tid   = threadIdx.x;
    const int warp  = tid >> 5;
    const int lane  = tid & 31;
    const int blk   = blockIdx.x;
    const int batch = blk >> 3;
    const int rank  = blk & 7;
    const int cg    = tid >> 4;     // column group (16 cols)
    const int rc    = tid & 15;     // row chunk

    // preload uint8 slab (128 rows, padded to 65 uint4 stride)
    {
        const uint4* src = (const uint4*)(d_C8 + ((size_t)batch << 20) + ((size_t)rank << 17));
#pragma unroll
        for (int j = 0; j < 8; j++) {
            int g = tid + 1024 * j;
            slab[(g >> 6) * 65 + (g & 63)] = src[g];
        }
    }
    sv[tid] = __float2half(1.0f / NPTS);
    if (tid == 0) saux[0] = 0.0f;

    const float invM = 1.0f / __uint_as_float(d_maxbits);
    const float qsc  = invM * (2.0f / 255.0f);
    float* vp_mine = d_vpart + (batch * 8 + rank) * NPTS;
    const float* vp_all = d_vpart + batch * 8 * NPTS;
    const unsigned KB = 0x64006400u;
    const __half2 kb = *(const __half2*)&KB;
    __syncthreads();

    unsigned step = 0;
    for (int iter = 0; iter < INT8_IT; iter++) {
        // ---- u (local rows, smem slab)
        float s0, s1, s2, s3;
        dot4q_s(slab + warp * 4 * 65, (const uint4*)sv, lane, s0, s1, s2, s3);
        WARP_RED4(s0, s1, s2, s3)
        if (lane < 4) {
            float s = (lane == 0) ? s0 : (lane == 1) ? s1 : (lane == 2) ? s2 : s3;
            float uv = 1.0f / (fmaf(qsc, s, EPS_SK));
            suh[warp * 4 + lane] = __float2half(uv);
        }
        __syncthreads();

        // ---- column partials from own slab (rows rc+16j, bank-safe)
        {
            __half2 z = __floats2half2_rn(0.f, 0.f);
            __half2 acc[8] = {z, z, z, z, z, z, z, z};
#pragma unroll
            for (int j = 0; j < 8; j++) {
                int r = rc + 16 * j;
                uint4 q = slab[r * 65 + cg];
                __half2 u2 = __half2half2(suh[r]);
                CDEC(q.x, acc[0], acc[1], u2, kb)
                CDEC(q.y, acc[2], acc[3], u2, kb)
                CDEC(q.z, acc[4], acc[5], u2, kb)
                CDEC(q.w, acc[6], acc[7], u2, kb)
            }
#pragma unroll
            for (int h = 0; h < 8; h++) sred[(cg * 8 + h) * 17 + rc] = acc[h];
        }
        __syncthreads();
        if (tid < 512) {
            const __half2* p = sred + tid * 17;
            float fx = 0.f, fy = 0.f;
#pragma unroll
            for (int k2 = 0; k2 < 16; k2++) {
                float2 f = __half22float2(p[k2]);
                fx += f.x; fy += f.y;
            }
            int m0 = 16 * (tid >> 3) + 2 * (tid & 7);
            float2 st; st.x = fx; st.y = fy;
            *(float2*)(vp_mine + m0) = st;
        }
        batch_barrier(batch, 8 * (++step));
        // ---- v recompute (identical in all blocks of the batch)
        {
            float a = 0.f;
#pragma unroll
            for (int k = 0; k < 8; k++) a += vp_all[k * NPTS + tid];
            sv[tid] = __float2half(1.0f / (fmaf(qsc, a, EPS_SK)));
        }
        __syncthreads();
    }

    // ---- polish iterations: same structure on fp16 C from global
    const __half* Cb = d_C + ((size_t)batch << 20) + ((size_t)rank << 17);
    float last_a = 0.0f;   // this thread's final column-sum (C^T u)_tid
    for (int iter = 0; iter < POLISH_IT; iter++) {
        float s0, s1, s2, s3;
        dot4h(Cb + (size_t)(warp * 4) * NPTS, (const __half2*)sv, lane, s0, s1, s2, s3);
        WARP_RED4(s0, s1, s2, s3)
        if (lane < 4) {
            float s = (lane == 0) ? s0 : (lane == 1) ? s1 : (lane == 2) ? s2 : s3;
            float uv = 1.0f / (fmaf(invM, s, EPS_SK));
            suh[warp * 4 + lane] = __float2half(uv);
        }
        __syncthreads();
        {
            __half2 z = __floats2half2_rn(0.f, 0.f);
            __half2 acc[8] = {z, z, z, z, z, z, z, z};
#pragma unroll
            for (int j = 0; j < 8; j++) {
                int r = rc + 16 * j;
                const uint4* gq = (const uint4*)(Cb + (size_t)r * NPTS) + 2 * cg;
                uint4 q0 = gq[0], q1 = gq[1];
                __half2 u2 = __half2half2(suh[r]);
                acc[0] = __hfma2(h2u(q0.x), u2, acc[0]);
                acc[1] = __hfma2(h2u(q0.y), u2, acc[1]);
                acc[2] = __hfma2(h2u(q0.z), u2, acc[2]);
                acc[3] = __hfma2(h2u(q0.w), u2, acc[3]);
                acc[4] = __hfma2(h2u(q1.x), u2, acc[4]);
                acc[5] = __hfma2(h2u(q1.y), u2, acc[5]);
                acc[6] = __hfma2(h2u(q1.z), u2, acc[6]);
                acc[7] = __hfma2(h2u(q1.w), u2, acc[7]);
            }
#pragma unroll
            for (int h = 0; h < 8; h++) sred[(cg * 8 + h) * 17 + rc] = acc[h];
        }
        __syncthreads();
        if (tid < 512) {
            const __half2* p = sred + tid * 17;
            float fx = 0.f, fy = 0.f;
#pragma unroll
            for (int k2 = 0; k2 < 16; k2++) {
                float2 f = __half22float2(p[k2]);
                fx += f.x; fy += f.y;
            }
            int m0 = 16 * (tid >> 3) + 2 * (tid & 7);
            float2 st; st.x = fx; st.y = fy;
            *(float2*)(vp_mine + m0) = st;
        }
        batch_barrier(batch, 8 * (++step));
        {
            float a = 0.f;
#pragma unroll
            for (int k = 0; k < 8; k++) a += vp_all[k * NPTS + tid];
            last_a = a;
            sv[tid] = __float2half(1.0f / (fmaf(invM, a, EPS_SK)));
        }
        __syncthreads();
    }

    // ---- distance = invM * Σ_j a_j v_j  (a_j = (C^T u)_j from last polish,
    //      v_j = 1/(invM a_j + eps)) — algebraically equal to u·C·v.
    {
        float v  = 1.0f / (fmaf(invM, last_a, EPS_SK));
        float c  = invM * last_a * v;
#pragma unroll
        for (int o = 16; o; o >>= 1) c += __shfl_xor_sync(0xffffffffu, c, o);
        if (lane == 0) atomicAdd(&saux[0], c);
        __syncthreads();
        if (tid == 0 && rank == 0) atomicAdd(out, saux[0] * (1.0f / BATCHES));
    }
}

// ---------------- launch ----------------------------------------------------
extern "C" void kernel_launch(void* const* d_in, const int* in_sizes, int n_in,
                              void* d_out, int out_size) {
    (void)in_sizes; (void)n_in; (void)out_size;
    const float* x = (const float*)d_in[0];
    const float* y = (const float*)d_in[1];
    float* out = (float*)d_out;

    static int attr_set = 0;
    if (!attr_set) {
        cudaFuncSetAttribute(sinkhorn_kernel,
                             cudaFuncAttributeMaxDynamicSharedMemorySize, SK_DSMEM);
        attr_set = 1;
    }

    normc_kernel<<<4096, 256>>>(x, y, out);
    dim3 g(8, 8, 16);
    gemm_cost_mma<<<g, 256>>>();
    sinkhorn_kernel<<<SK_GRID, 1024, SK_DSMEM>>>(out);
}

// round 12
// speedup vs baseline: 1.7908x; 1.1347x over previous
#include <cuda_runtime.h>
#include <cuda_fp16.h>
#include <cstdint>

#define BATCHES 16
#define NPTS    1024
#define DIMS    1024
#define EPS_SK  1e-3f
#define INT8_IT   10
#define POLISH_IT  2

// ---------------- scratch (static device globals; no runtime alloc) --------
__device__ __half         d_C [BATCHES * NPTS * NPTS];   // fp16 C (polish, 32 MB)
__device__ unsigned char  d_C8[BATCHES * NPTS * NPTS];   // uint8 C = rn(255*C/2) (16 MB)
__device__ __half  d_xh[BATCHES * NPTS * DIMS];
__device__ __half  d_yh[BATCHES * NPTS * DIMS];
__device__ float   d_vpart[BATCHES * 8 * NPTS];          // per-rank column partials
__device__ unsigned d_maxbits;
__device__ unsigned d_bar[BATCHES * 32];                 // per-batch barrier ctrs

// ---------------- normalize rows -> fp16 (+ fused per-replay init) ----------
__global__ void normc_kernel(const float* __restrict__ x,
                             const float* __restrict__ y,
                             float* __restrict__ out) {
    if (blockIdx.x == 0) {
        for (int t = threadIdx.x; t < BATCHES * 32; t += blockDim.x) d_bar[t] = 0u;
        if (threadIdx.x == 0) { d_maxbits = 0u; out[0] = 0.0f; }
    }
    int gw   = blockIdx.x * 8 + (threadIdx.x >> 5);
    int lane = threadIdx.x & 31;
    const float* src;
    __half* dst;
    if (gw < BATCHES * NPTS) { src = x + (size_t)gw * DIMS;                     dst = d_xh + (size_t)gw * DIMS; }
    else                     { src = y + (size_t)(gw - BATCHES * NPTS) * DIMS;  dst = d_yh + (size_t)(gw - BATCHES * NPTS) * DIMS; }
    const float4* p = (const float4*)src;
    float4 f[8];
    float ss = 0.0f;
#pragma unroll
    for (int k = 0; k < 8; k++) {
        f[k] = p[lane + 32 * k];
        ss += f[k].x * f[k].x + f[k].y * f[k].y + f[k].z * f[k].z + f[k].w * f[k].w;
    }
#pragma unroll
    for (int o = 16; o; o >>= 1) ss += __shfl_xor_sync(0xffffffffu, ss, o);
    float inv = 1.0f / fmaxf(sqrtf(ss), 1e-12f);
#pragma unroll
    for (int k = 0; k < 8; k++) {
        __half2 h0 = __floats2half2_rn(f[k].x * inv, f[k].y * inv);
        __half2 h1 = __floats2half2_rn(f[k].z * inv, f[k].w * inv);
        uint2 u; u.x = *(unsigned*)&h0; u.y = *(unsigned*)&h1;
        *(uint2*)(dst + (size_t)(lane + 32 * k) * 4) = u;
    }
}

// ---------------- tensor-core cost GEMM (3-stage cp.async pipeline) ---------
#define SSTRIDE 40
#define CTSTR   136
#define GEMM_STG_B (128 * SSTRIDE * 2)            // 10240 B per stage buffer
#define GEMM_DSMEM (6 * GEMM_STG_B)               // 3 stages x (A,B) = 61440 B

#define CP_ASYNC16(saddr, gptr) \
    asm volatile("cp.async.cg.shared.global [%0], [%1], 16;" :: "r"(saddr), "l"(gptr))
#define CP_COMMIT() asm volatile("cp.async.commit_group;")
#define CP_WAIT0()  asm volatile("cp.async.wait_group 0;" ::: "memory")
#define CP_WAIT1()  asm volatile("cp.async.wait_group 1;" ::: "memory")

#define LDSM_X4(r0, r1, r2, r3, addr)                                          \
    asm volatile("ldmatrix.sync.aligned.m8n8.x4.shared.b16 {%0,%1,%2,%3}, [%4];" \
        : "=r"(r0), "=r"(r1), "=r"(r2), "=r"(r3) : "r"(addr))
#define LDSM_X2(r0, r1, addr)                                                  \
    asm volatile("ldmatrix.sync.aligned.m8n8.x2.shared.b16 {%0,%1}, [%2];"     \
        : "=r"(r0), "=r"(r1) : "r"(addr))

__device__ __forceinline__ void mma16816(float* d, const unsigned* a, const unsigned* b) {
    asm volatile(
        "mma.sync.aligned.m16n8k16.row.col.f32.f16.f16.f32 "
        "{%0,%1,%2,%3}, {%4,%5,%6,%7}, {%8,%9}, {%0,%1,%2,%3};"
        : "+f"(d[0]), "+f"(d[1]), "+f"(d[2]), "+f"(d[3])
        : "r"(a[0]), "r"(a[1]), "r"(a[2]), "r"(a[3]), "r"(b[0]), "r"(b[1]));
}

__device__ __forceinline__ unsigned char q8(__half h) {
    return (unsigned char)__float2uint_rn(__saturatef(__half2float(h) * 0.5f) * 255.0f);
}

__global__ void __launch_bounds__(256, 2)
gemm_cost_mma(void) {
    extern __shared__ __align__(16) __half gsm[];   // 3-stage staging / epilogue Ct
    __shared__ float s_wmax[8];

    const int tid  = threadIdx.x;
    const int warp = tid >> 5;
    const int lane = tid & 31;
    const int wm   = warp >> 2;
    const int wn   = warp & 3;
    const int lq   = lane >> 2;
    const int lr4  = lane & 3;
    const int bz   = blockIdx.z;
    const int n0   = blockIdx.y * 128;
    const int m0   = blockIdx.x * 128;

    const __half* xb = d_xh + ((size_t)bz << 20);
    const __half* yb = d_yh + ((size_t)bz << 20);

    const int lrow = tid >> 2;
    const int lseg = tid & 3;
    const __half* gxa = xb + (size_t)(n0 + lrow) * DIMS + lseg * 8;
    const __half* gxb = xb + (size_t)(n0 + lrow + 64) * DIMS + lseg * 8;
    const __half* gya = yb + (size_t)(m0 + lrow) * DIMS + lseg * 8;
    const __half* gyb = yb + (size_t)(m0 + lrow + 64) * DIMS + lseg * 8;

    const uint32_t smem_u32 = (uint32_t)__cvta_generic_to_shared(gsm);
    const uint32_t STG = (uint32_t)GEMM_STG_B;
    const uint32_t BBASE = 3u * STG;                 // B region after 3 A stages
    const uint32_t sAa = smem_u32 + 2u * (lrow * SSTRIDE + lseg * 8);
    const uint32_t sAb = smem_u32 + 2u * ((lrow + 64) * SSTRIDE + lseg * 8);
    const uint32_t sBa = smem_u32 + BBASE + 2u * (lrow * SSTRIDE + lseg * 8);
    const uint32_t sBb = smem_u32 + BBASE + 2u * ((lrow + 64) * SSTRIDE + lseg * 8);

#define LOAD_STAGE(stg, k0)                                   \
    { CP_ASYNC16(sAa + (stg) * STG, gxa + (k0));              \
      CP_ASYNC16(sAb + (stg) * STG, gxb + (k0));              \
      CP_ASYNC16(sBa + (stg) * STG, gya + (k0));              \
      CP_ASYNC16(sBb + (stg) * STG, gyb + (k0));              \
      CP_COMMIT(); }

    const int arow_l = (lane & 7) + ((lane >> 3) & 1) * 8;
    const int acol_l = (lane >> 4) * 8;
    const int brow_l = lane & 7;
    const int bcol_l = ((lane >> 3) & 1) * 8;

    float acc[4][4][4];
#pragma unroll
    for (int i = 0; i < 4; i++)
#pragma unroll
        for (int j = 0; j < 4; j++)
#pragma unroll
            for (int q = 0; q < 4; q++) acc[i][j][q] = 0.0f;

    LOAD_STAGE(0u, 0);
    LOAD_STAGE(1u, 32);

    unsigned stg = 0;   // buffer index of current k-iter (it % 3)
    for (int it = 0; it < 32; it++) {
        if (it < 31) CP_WAIT1(); else CP_WAIT0();
        __syncthreads();
        if (it < 30) {
            unsigned nstg = stg + 2; if (nstg >= 3) nstg -= 3;
            LOAD_STAGE(nstg, (it + 2) * 32);
        }
        const uint32_t aS = smem_u32 + stg * STG;
        const uint32_t bS = smem_u32 + BBASE + stg * STG;
#pragma unroll
        for (int ks = 0; ks < 32; ks += 16) {
            unsigned a[4][4], b[4][2];
#pragma unroll
            for (int i = 0; i < 4; i++) {
                uint32_t ad = aS + 2u * ((wm * 64 + i * 16 + arow_l) * SSTRIDE + ks + acol_l);
                LDSM_X4(a[i][0], a[i][1], a[i][2], a[i][3], ad);
            }
#pragma unroll
            for (int j = 0; j < 4; j++) {
                uint32_t bd = bS + 2u * ((wn * 32 + j * 8 + brow_l) * SSTRIDE + ks + bcol_l);
                LDSM_X2(b[j][0], b[j][1], bd);
            }
#pragma unroll
            for (int i = 0; i < 4; i++)
#pragma unroll
                for (int j = 0; j < 4; j++) mma16816(acc[i][j], a[i], b[j]);
        }
        stg = (stg == 2) ? 0u : stg + 1u;
    }
    __syncthreads();
#undef LOAD_STAGE

    // epilogue: cost = 1 - dot; stage fp16 tile, write C fp16 + C8 uint8
    __half* Ct = gsm;   // 128 x CTSTR halves = 34816 B < GEMM_DSMEM
    float mx = 0.0f;
#pragma unroll
    for (int i = 0; i < 4; i++) {
        const int r0 = wm * 64 + i * 16 + lq;
#pragma unroll
        for (int j = 0; j < 4; j++) {
            const int c = wn * 32 + j * 8 + lr4 * 2;
            float c00 = 1.0f - acc[i][j][0];
            float c01 = 1.0f - acc[i][j][1];
            float c10 = 1.0f - acc[i][j][2];
            float c11 = 1.0f - acc[i][j][3];
            mx = fmaxf(mx, fmaxf(fmaxf(c00, c01), fmaxf(c10, c11)));
            *(__half2*)(Ct + r0 * CTSTR + c)       = __floats2half2_rn(c00, c01);
            *(__half2*)(Ct + (r0 + 8) * CTSTR + c) = __floats2half2_rn(c10, c11);
        }
    }
    __syncthreads();

    const size_t base = (size_t)bz << 20;
    const int row = tid >> 1;
    const int off = (tid & 1) * 64;
    {   // C fp16 rows
#pragma unroll
        for (int u = 0; u < 8; u++) {
            uint4 q = *(const uint4*)(Ct + row * CTSTR + off + u * 8);
            *(uint4*)(d_C + base + (size_t)(n0 + row) * NPTS + m0 + off + u * 8) = q;
        }
    }
    {   // C8 uint8 rows
#pragma unroll
        for (int u = 0; u < 4; u++) {
            const __half* s = Ct + row * CTSTR + off + u * 16;
            uint4 q;
            unsigned w[4];
#pragma unroll
            for (int p = 0; p < 4; p++) {
                w[p] = (unsigned)q8(s[4 * p]) | ((unsigned)q8(s[4 * p + 1]) << 8) |
                       ((unsigned)q8(s[4 * p + 2]) << 16) | ((unsigned)q8(s[4 * p + 3]) << 24);
            }
            q.x = w[0]; q.y = w[1]; q.z = w[2]; q.w = w[3];
            *(uint4*)(d_C8 + base + (size_t)(n0 + row) * NPTS + m0 + off + u * 16) = q;
        }
    }

#pragma unroll
    for (int o = 16; o; o >>= 1) mx = fmaxf(mx, __shfl_xor_sync(0xffffffffu, mx, o));
    if (lane == 0) s_wmax[warp] = mx;
    __syncthreads();
    if (tid == 0) {
        float bm = s_wmax[0];
#pragma unroll
        for (int w = 1; w < 8; w++) bm = fmaxf(bm, s_wmax[w]);
        atomicMax(&d_maxbits, __float_as_uint(bm));
    }
}

// ---------------- persistent Sinkhorn: one barrier/iter, no C^T -------------
#define SK_GRID 128
#define SK_DSMEM 170768

// release/acquire barrier (cooperative-groups grid-sync pattern)
__device__ __forceinline__ void batch_barrier(int batch, unsigned target) {
    __syncthreads();
    if (threadIdx.x == 0) {
        unsigned* ctr = &d_bar[batch * 32];
        asm volatile("red.release.gpu.global.add.u32 [%0], %1;"
                     :: "l"(ctr), "r"(1u) : "memory");
        unsigned v;
        do {
            asm volatile("ld.acquire.gpu.global.u32 %0, [%1];"
                         : "=r"(v) : "l"(ctr) : "memory");
        } while (v < target);
    }
    __syncthreads();
}

__device__ __forceinline__ __half2 h2u(unsigned u) { return *(__half2*)&u; }

// uint8 row dot (row as 2 uint4 per lane-chunk) vs v chunks
__device__ __forceinline__ float dotrow_q(uint4 q0, uint4 q1,
                                          const uint4 va0, const uint4 va1,
                                          const uint4 vb0, const uint4 vb1) {
    const unsigned K = 0x64006400u;
    const __half2 k = *(const __half2*)&K;
    __half2 A = __floats2half2_rn(0.f, 0.f);
    __half2 B = A;
#define QW(w, v01, v23)                                                        \
    { unsigned rlo, rhi;                                                       \
      asm("prmt.b32 %0,%1,%2,0x5140;" : "=r"(rlo) : "r"(w), "r"(0x64646464u)); \
      asm("prmt.b32 %0,%1,%2,0x7362;" : "=r"(rhi) : "r"(w), "r"(0x64646464u)); \
      A = __hfma2(__hsub2(*(__half2*)&rlo, k), *(const __half2*)&(v01), A);    \
      B = __hfma2(__hsub2(*(__half2*)&rhi, k), *(const __half2*)&(v23), B); }
    QW(q0.x, va0.x, va0.y) QW(q0.y, va0.z, va0.w)
    QW(q0.z, va1.x, va1.y) QW(q0.w, va1.z, va1.w)
    QW(q1.x, vb0.x, vb0.y) QW(q1.y, vb0.z, vb0.w)
    QW(q1.z, vb1.x, vb1.y) QW(q1.w, vb1.z, vb1.w)
#undef QW
    return __low2float(A) + __high2float(A) + __low2float(B) + __high2float(B);
}

// 4 row dots from the padded smem slab (stride 65 uint4)
__device__ __forceinline__ void dot4q_s(const uint4* __restrict__ sw,
                                        const uint4* __restrict__ sv4, int lane,
                                        float& s0, float& s1, float& s2, float& s3) {
    const uint4 va0 = sv4[2 * lane], va1 = sv4[2 * lane + 1];
    const uint4 vb0 = sv4[64 + 2 * lane], vb1 = sv4[64 + 2 * lane + 1];
    s0 = dotrow_q(sw[lane],       sw[32 + lane],  va0, va1, vb0, vb1);
    s1 = dotrow_q(sw[65 + lane],  sw[97 + lane],  va0, va1, vb0, vb1);
    s2 = dotrow_q(sw[130 + lane], sw[162 + lane], va0, va1, vb0, vb1);
    s3 = dotrow_q(sw[195 + lane], sw[227 + lane], va0, va1, vb0, vb1);
}

// fp16 4-row dot from global C
__device__ __forceinline__ void dot4h(const __half* __restrict__ rowbase,
                                      const __half2* __restrict__ sv2, int lane,
                                      float& s0, float& s1, float& s2, float& s3) {
    const uint4* r = (const uint4*)rowbase;
    __half2 z = __floats2half2_rn(0.f, 0.f);
    __half2 a0a = z, a0b = z, a1a = z, a1b = z, a2a = z, a2b = z, a3a = z, a3b = z;
#pragma unroll
    for (int k = 0; k < 4; k++) {
        int idx = lane + 32 * k;
        uint4 vv = *(const uint4*)(sv2 + idx * 4);
        __half2 v0 = h2u(vv.x), v1 = h2u(vv.y), v2 = h2u(vv.z), v3 = h2u(vv.w);
        uint4 q0 = r[idx];
        uint4 q1 = r[idx + 128];
        uint4 q2 = r[idx + 256];
        uint4 q3 = r[idx + 384];
        a0a = __hfma2(h2u(q0.x), v0, a0a); a0b = __hfma2(h2u(q0.y), v1, a0b);
        a0a = __hfma2(h2u(q0.z), v2, a0a); a0b = __hfma2(h2u(q0.w), v3, a0b);
        a1a = __hfma2(h2u(q1.x), v0, a1a); a1b = __hfma2(h2u(q1.y), v1, a1b);
        a1a = __hfma2(h2u(q1.z), v2, a1a); a1b = __hfma2(h2u(q1.w), v3, a1b);
        a2a = __hfma2(h2u(q2.x), v0, a2a); a2b = __hfma2(h2u(q2.y), v1, a2b);
        a2a = __hfma2(h2u(q2.z), v2, a2a); a2b = __hfma2(h2u(q2.w), v3, a2b);
        a3a = __hfma2(h2u(q3.x), v0, a3a); a3b = __hfma2(h2u(q3.y), v1, a3b);
        a3a = __hfma2(h2u(q3.z), v2, a3a); a3b = __hfma2(h2u(q3.w), v3, a3b);
    }
    s0 = __low2float(a0a) + __high2float(a0a) + __low2float(a0b) + __high2float(a0b);
    s1 = __low2float(a1a) + __high2float(a1a) + __low2float(a1b) + __high2float(a1b);
    s2 = __low2float(a2a) + __high2float(a2a) + __low2float(a2b) + __high2float(a2b);
    s3 = __low2float(a3a) + __high2float(a3a) + __low2float(a3b) + __high2float(a3b);
}

#define WARP_RED4(s0, s1, s2, s3)                          \
    _Pragma("unroll")                                      \
    for (int o = 16; o; o >>= 1) {                         \
        s0 += __shfl_xor_sync(0xffffffffu, s0, o);         \
        s1 += __shfl_xor_sync(0xffffffffu, s1, o);         \
        s2 += __shfl_xor_sync(0xffffffffu, s2, o);         \
        s3 += __shfl_xor_sync(0xffffffffu, s3, o);         \
    }

// decode one uint (4 uint8 cols) and accumulate into 2 half2 col-accumulators
#define CDEC(w, aE, aO, u2, kb)                                                \
    { unsigned rlo, rhi;                                                       \
      asm("prmt.b32 %0,%1,%2,0x5140;" : "=r"(rlo) : "r"(w), "r"(0x64646464u)); \
      asm("prmt.b32 %0,%1,%2,0x7362;" : "=r"(rhi) : "r"(w), "r"(0x64646464u)); \
      aE = __hfma2(__hsub2(*(__half2*)&rlo, kb), u2, aE);                      \
      aO = __hfma2(__hsub2(*(__half2*)&rhi, kb), u2, aO); }

__global__ void __launch_bounds__(1024, 1)
sinkhorn_kernel(float* __restrict__ out) {
    extern __shared__ __align__(16) unsigned char sk[];
    uint4*   slab = (uint4*)sk;
    __half*  sv   = (__half*)(sk + 133120);
    __half*  suh  = (__half*)(sk + 135168);
    __half2* sred = (__half2*)(sk + 135936);
    float*   saux = (float*)(sk + 170752);

    const int tid   = threadIdx.x;
    const int warp  = tid >> 5;
    const int lane  = tid & 31;
    const int blk   = blockIdx.x;
    const int batch = blk >> 3;
    const int rank  = blk & 7;
    const int cg    = tid >> 4;     // column group (16 cols)
    const int rc    = tid & 15;     // row chunk

    // preload uint8 slab (128 rows, padded to 65 uint4 stride)
    {
        const uint4* src = (const uint4*)(d_C8 + ((size_t)batch << 20) + ((size_t)rank << 17));
#pragma unroll
        for (int j = 0; j < 8; j++) {
            int g = tid + 1024 * j;
            slab[(g >> 6) * 65 + (g & 63)] = src[g];
        }
    }
    sv[tid] = __float2half(1.0f / NPTS);
    if (tid == 0) saux[0] = 0.0f;

    const float invM = 1.0f / __uint_as_float(d_maxbits);
    const float qsc  = invM * (2.0f / 255.0f);
    float* vp_mine = d_vpart + (batch * 8 + rank) * NPTS;
    const float* vp_all = d_vpart + batch * 8 * NPTS;
    const unsigned KB = 0x64006400u;
    const __half2 kb = *(const __half2*)&KB;
    __syncthreads();

    unsigned step = 0;
    for (int iter = 0; iter < INT8_IT; iter++) {
        // ---- u (local rows, smem slab)
        float s0, s1, s2, s3;
        dot4q_s(slab + warp * 4 * 65, (const uint4*)sv, lane, s0, s1, s2, s3);
        WARP_RED4(s0, s1, s2, s3)
        if (lane < 4) {
            float s = (lane == 0) ? s0 : (lane == 1) ? s1 : (lane == 2) ? s2 : s3;
            float uv = 1.0f / (fmaf(qsc, s, EPS_SK));
            suh[warp * 4 + lane] = __float2half(uv);
        }
        __syncthreads();

        // ---- column partials from own slab (rows rc+16j, bank-safe)
        {
            __half2 z = __floats2half2_rn(0.f, 0.f);
            __half2 acc[8] = {z, z, z, z, z, z, z, z};
#pragma unroll
            for (int j = 0; j < 8; j++) {
                int r = rc + 16 * j;
                uint4 q = slab[r * 65 + cg];
                __half2 u2 = __half2half2(suh[r]);
                CDEC(q.x, acc[0], acc[1], u2, kb)
                CDEC(q.y, acc[2], acc[3], u2, kb)
                CDEC(q.z, acc[4], acc[5], u2, kb)
                CDEC(q.w, acc[6], acc[7], u2, kb)
            }
#pragma unroll
            for (int h = 0; h < 8; h++) sred[(cg * 8 + h) * 17 + rc] = acc[h];
        }
        __syncthreads();
        if (tid < 512) {
            const __half2* p = sred + tid * 17;
            float fx = 0.f, fy = 0.f;
#pragma unroll
            for (int k2 = 0; k2 < 16; k2++) {
                float2 f = __half22float2(p[k2]);
                fx += f.x; fy += f.y;
            }
            int m0 = 16 * (tid >> 3) + 2 * (tid & 7);
            float2 st; st.x = fx; st.y = fy;
            *(float2*)(vp_mine + m0) = st;
        }
        batch_barrier(batch, 8 * (++step));
        // ---- v recompute (identical in all blocks of the batch)
        {
            float a = 0.f;
#pragma unroll
            for (int k = 0; k < 8; k++) a += vp_all[k * NPTS + tid];
            sv[tid] = __float2half(1.0f / (fmaf(qsc, a, EPS_SK)));
        }
        __syncthreads();
    }

    // ---- polish iterations: same structure on fp16 C from global
    const __half* Cb = d_C + ((size_t)batch << 20) + ((size_t)rank << 17);
    float last_a = 0.0f;   // this thread's final column-sum (C^T u)_tid
    for (int iter = 0; iter < POLISH_IT; iter++) {
        float s0, s1, s2, s3;
        dot4h(Cb + (size_t)(warp * 4) * NPTS, (const __half2*)sv, lane, s0, s1, s2, s3);
        WARP_RED4(s0, s1, s2, s3)
        if (lane < 4) {
            float s = (lane == 0) ? s0 : (lane == 1) ? s1 : (lane == 2) ? s2 : s3;
            float uv = 1.0f / (fmaf(invM, s, EPS_SK));
            suh[warp * 4 + lane] = __float2half(uv);
        }
        __syncthreads();
        {
            __half2 z = __floats2half2_rn(0.f, 0.f);
            __half2 acc[8] = {z, z, z, z, z, z, z, z};
#pragma unroll
            for (int j = 0; j < 8; j++) {
                int r = rc + 16 * j;
                const uint4* gq = (const uint4*)(Cb + (size_t)r * NPTS) + 2 * cg;
                uint4 q0 = gq[0], q1 = gq[1];
                __half2 u2 = __half2half2(suh[r]);
                acc[0] = __hfma2(h2u(q0.x), u2, acc[0]);
                acc[1] = __hfma2(h2u(q0.y), u2, acc[1]);
                acc[2] = __hfma2(h2u(q0.z), u2, acc[2]);
                acc[3] = __hfma2(h2u(q0.w), u2, acc[3]);
                acc[4] = __hfma2(h2u(q1.x), u2, acc[4]);
                acc[5] = __hfma2(h2u(q1.y), u2, acc[5]);
                acc[6] = __hfma2(h2u(q1.z), u2, acc[6]);
                acc[7] = __hfma2(h2u(q1.w), u2, acc[7]);
            }
#pragma unroll
            for (int h = 0; h < 8; h++) sred[(cg * 8 + h) * 17 + rc] = acc[h];
        }
        __syncthreads();
        if (tid < 512) {
            const __half2* p = sred + tid * 17;
            float fx = 0.f, fy = 0.f;
#pragma unroll
            for (int k2 = 0; k2 < 16; k2++) {
                float2 f = __half22float2(p[k2]);
                fx += f.x; fy += f.y;
            }
            int m0 = 16 * (tid >> 3) + 2 * (tid & 7);
            float2 st; st.x = fx; st.y = fy;
            *(float2*)(vp_mine + m0) = st;
        }
        batch_barrier(batch, 8 * (++step));
        {
            float a = 0.f;
#pragma unroll
            for (int k = 0; k < 8; k++) a += vp_all[k * NPTS + tid];
            last_a = a;
            sv[tid] = __float2half(1.0f / (fmaf(invM, a, EPS_SK)));
        }
        __syncthreads();
    }

    // ---- distance = invM * Σ_j a_j v_j  (stationarity-fused final reduction)
    {
        float v  = 1.0f / (fmaf(invM, last_a, EPS_SK));
        float c  = invM * last_a * v;
#pragma unroll
        for (int o = 16; o; o >>= 1) c += __shfl_xor_sync(0xffffffffu, c, o);
        if (lane == 0) atomicAdd(&saux[0], c);
        __syncthreads();
        if (tid == 0 && rank == 0) atomicAdd(out, saux[0] * (1.0f / BATCHES));
    }
}

// ---------------- launch ----------------------------------------------------
extern "C" void kernel_launch(void* const* d_in, const int* in_sizes, int n_in,
                              void* d_out, int out_size) {
    (void)in_sizes; (void)n_in; (void)out_size;
    const float* x = (const float*)d_in[0];
    const float* y = (const float*)d_in[1];
    float* out = (float*)d_out;

    static int attr_set = 0;
    if (!attr_set) {
        cudaFuncSetAttribute(sinkhorn_kernel,
                             cudaFuncAttributeMaxDynamicSharedMemorySize, SK_DSMEM);
        cudaFuncSetAttribute(gemm_cost_mma,
                             cudaFuncAttributeMaxDynamicSharedMemorySize, GEMM_DSMEM);
        attr_set = 1;
    }

    normc_kernel<<<4096, 256>>>(x, y, out);
    dim3 g(8, 8, 16);
    gemm_cost_mma<<<g, 256, GEMM_DSMEM>>>();
    sinkhorn_kernel<<<SK_GRID, 1024, SK_DSMEM>>>(out);
}

// round 13
// speedup vs baseline: 2.0290x; 1.1330x over previous
#include <cuda_runtime.h>
#include <cuda_fp16.h>
#include <cstdint>

#define BATCHES 16
#define NPTS    1024
#define DIMS    1024
#define EPS_SK  1e-3f
#define INT8_IT    8
#define POLISH_IT  1

// ---------------- scratch (static device globals; no runtime alloc) --------
__device__ __half         d_C [BATCHES * NPTS * NPTS];   // fp16 C (polish, 32 MB)
__device__ unsigned char  d_C8[BATCHES * NPTS * NPTS];   // uint8 C = rn(255*C/2) (16 MB)
__device__ __half  d_xh[BATCHES * NPTS * DIMS];
__device__ __half  d_yh[BATCHES * NPTS * DIMS];
__device__ float   d_vpart[BATCHES * 8 * NPTS];          // per-rank column partials
__device__ unsigned d_maxbits;
__device__ unsigned d_bar[BATCHES * 32];                 // per-batch barrier ctrs

// ---------------- normalize rows -> fp16 (+ fused per-replay init) ----------
__global__ void normc_kernel(const float* __restrict__ x,
                             const float* __restrict__ y,
                             float* __restrict__ out) {
    if (blockIdx.x == 0) {
        for (int t = threadIdx.x; t < BATCHES * 32; t += blockDim.x) d_bar[t] = 0u;
        if (threadIdx.x == 0) { d_maxbits = 0u; out[0] = 0.0f; }
    }
    int gw   = blockIdx.x * 8 + (threadIdx.x >> 5);
    int lane = threadIdx.x & 31;
    const float* src;
    __half* dst;
    if (gw < BATCHES * NPTS) { src = x + (size_t)gw * DIMS;                     dst = d_xh + (size_t)gw * DIMS; }
    else                     { src = y + (size_t)(gw - BATCHES * NPTS) * DIMS;  dst = d_yh + (size_t)(gw - BATCHES * NPTS) * DIMS; }
    const float4* p = (const float4*)src;
    float4 f[8];
    float ss = 0.0f;
#pragma unroll
    for (int k = 0; k < 8; k++) {
        f[k] = p[lane + 32 * k];
        ss += f[k].x * f[k].x + f[k].y * f[k].y + f[k].z * f[k].z + f[k].w * f[k].w;
    }
#pragma unroll
    for (int o = 16; o; o >>= 1) ss += __shfl_xor_sync(0xffffffffu, ss, o);
    float inv = 1.0f / fmaxf(sqrtf(ss), 1e-12f);
#pragma unroll
    for (int k = 0; k < 8; k++) {
        __half2 h0 = __floats2half2_rn(f[k].x * inv, f[k].y * inv);
        __half2 h1 = __floats2half2_rn(f[k].z * inv, f[k].w * inv);
        uint2 u; u.x = *(unsigned*)&h0; u.y = *(unsigned*)&h1;
        *(uint2*)(dst + (size_t)(lane + 32 * k) * 4) = u;
    }
}

// ---------------- tensor-core cost GEMM (3-stage cp.async pipeline) ---------
#define SSTRIDE 40
#define CTSTR   136
#define GEMM_STG_B (128 * SSTRIDE * 2)            // 10240 B per stage buffer
#define GEMM_DSMEM (6 * GEMM_STG_B)               // 3 stages x (A,B) = 61440 B

#define CP_ASYNC16(saddr, gptr) \
    asm volatile("cp.async.cg.shared.global [%0], [%1], 16;" :: "r"(saddr), "l"(gptr))
#define CP_COMMIT() asm volatile("cp.async.commit_group;")
#define CP_WAIT0()  asm volatile("cp.async.wait_group 0;" ::: "memory")
#define CP_WAIT1()  asm volatile("cp.async.wait_group 1;" ::: "memory")

#define LDSM_X4(r0, r1, r2, r3, addr)                                          \
    asm volatile("ldmatrix.sync.aligned.m8n8.x4.shared.b16 {%0,%1,%2,%3}, [%4];" \
        : "=r"(r0), "=r"(r1), "=r"(r2), "=r"(r3) : "r"(addr))
#define LDSM_X2(r0, r1, addr)                                                  \
    asm volatile("ldmatrix.sync.aligned.m8n8.x2.shared.b16 {%0,%1}, [%2];"     \
        : "=r"(r0), "=r"(r1) : "r"(addr))

__device__ __forceinline__ void mma16816(float* d, const unsigned* a, const unsigned* b) {
    asm volatile(
        "mma.sync.aligned.m16n8k16.row.col.f32.f16.f16.f32 "
        "{%0,%1,%2,%3}, {%4,%5,%6,%7}, {%8,%9}, {%0,%1,%2,%3};"
        : "+f"(d[0]), "+f"(d[1]), "+f"(d[2]), "+f"(d[3])
        : "r"(a[0]), "r"(a[1]), "r"(a[2]), "r"(a[3]), "r"(b[0]), "r"(b[1]));
}

__device__ __forceinline__ unsigned char q8(__half h) {
    return (unsigned char)__float2uint_rn(__saturatef(__half2float(h) * 0.5f) * 255.0f);
}

__global__ void __launch_bounds__(256, 2)
gemm_cost_mma(void) {
    extern __shared__ __align__(16) __half gsm[];   // 3-stage staging / epilogue Ct
    __shared__ float s_wmax[8];

    const int tid  = threadIdx.x;
    const int warp = tid >> 5;
    const int lane = tid & 31;
    const int wm   = warp >> 2;
    const int wn   = warp & 3;
    const int lq   = lane >> 2;
    const int lr4  = lane & 3;
    const int bz   = blockIdx.z;
    const int n0   = blockIdx.y * 128;
    const int m0   = blockIdx.x * 128;

    const __half* xb = d_xh + ((size_t)bz << 20);
    const __half* yb = d_yh + ((size_t)bz << 20);

    const int lrow = tid >> 2;
    const int lseg = tid & 3;
    const __half* gxa = xb + (size_t)(n0 + lrow) * DIMS + lseg * 8;
    const __half* gxb = xb + (size_t)(n0 + lrow + 64) * DIMS + lseg * 8;
    const __half* gya = yb + (size_t)(m0 + lrow) * DIMS + lseg * 8;
    const __half* gyb = yb + (size_t)(m0 + lrow + 64) * DIMS + lseg * 8;

    const uint32_t smem_u32 = (uint32_t)__cvta_generic_to_shared(gsm);
    const uint32_t STG = (uint32_t)GEMM_STG_B;
    const uint32_t BBASE = 3u * STG;                 // B region after 3 A stages
    const uint32_t sAa = smem_u32 + 2u * (lrow * SSTRIDE + lseg * 8);
    const uint32_t sAb = smem_u32 + 2u * ((lrow + 64) * SSTRIDE + lseg * 8);
    const uint32_t sBa = smem_u32 + BBASE + 2u * (lrow * SSTRIDE + lseg * 8);
    const uint32_t sBb = smem_u32 + BBASE + 2u * ((lrow + 64) * SSTRIDE + lseg * 8);

#define LOAD_STAGE(stg, k0)                                   \
    { CP_ASYNC16(sAa + (stg) * STG, gxa + (k0));              \
      CP_ASYNC16(sAb + (stg) * STG, gxb + (k0));              \
      CP_ASYNC16(sBa + (stg) * STG, gya + (k0));              \
      CP_ASYNC16(sBb + (stg) * STG, gyb + (k0));              \
      CP_COMMIT(); }

    const int arow_l = (lane & 7) + ((lane >> 3) & 1) * 8;
    const int acol_l = (lane >> 4) * 8;
    const int brow_l = lane & 7;
    const int bcol_l = ((lane >> 3) & 1) * 8;

    float acc[4][4][4];
#pragma unroll
    for (int i = 0; i < 4; i++)
#pragma unroll
        for (int j = 0; j < 4; j++)
#pragma unroll
            for (int q = 0; q < 4; q++) acc[i][j][q] = 0.0f;

    LOAD_STAGE(0u, 0);
    LOAD_STAGE(1u, 32);

    unsigned stg = 0;   // buffer index of current k-iter (it % 3)
    for (int it = 0; it < 32; it++) {
        if (it < 31) CP_WAIT1(); else CP_WAIT0();
        __syncthreads();
        if (it < 30) {
            unsigned nstg = stg + 2; if (nstg >= 3) nstg -= 3;
            LOAD_STAGE(nstg, (it + 2) * 32);
        }
        const uint32_t aS = smem_u32 + stg * STG;
        const uint32_t bS = smem_u32 + BBASE + stg * STG;
#pragma unroll
        for (int ks = 0; ks < 32; ks += 16) {
            unsigned a[4][4], b[4][2];
#pragma unroll
            for (int i = 0; i < 4; i++) {
                uint32_t ad = aS + 2u * ((wm * 64 + i * 16 + arow_l) * SSTRIDE + ks + acol_l);
                LDSM_X4(a[i][0], a[i][1], a[i][2], a[i][3], ad);
            }
#pragma unroll
            for (int j = 0; j < 4; j++) {
                uint32_t bd = bS + 2u * ((wn * 32 + j * 8 + brow_l) * SSTRIDE + ks + bcol_l);
                LDSM_X2(b[j][0], b[j][1], bd);
            }
#pragma unroll
            for (int i = 0; i < 4; i++)
#pragma unroll
                for (int j = 0; j < 4; j++) mma16816(acc[i][j], a[i], b[j]);
        }
        stg = (stg == 2) ? 0u : stg + 1u;
    }
    __syncthreads();
#undef LOAD_STAGE

    // epilogue: cost = 1 - dot; stage fp16 tile, write C fp16 + C8 uint8
    __half* Ct = gsm;   // 128 x CTSTR halves = 34816 B < GEMM_DSMEM
    float mx = 0.0f;
#pragma unroll
    for (int i = 0; i < 4; i++) {
        const int r0 = wm * 64 + i * 16 + lq;
#pragma unroll
        for (int j = 0; j < 4; j++) {
            const int c = wn * 32 + j * 8 + lr4 * 2;
            float c00 = 1.0f - acc[i][j][0];
            float c01 = 1.0f - acc[i][j][1];
            float c10 = 1.0f - acc[i][j][2];
            float c11 = 1.0f - acc[i][j][3];
            mx = fmaxf(mx, fmaxf(fmaxf(c00, c01), fmaxf(c10, c11)));
            *(__half2*)(Ct + r0 * CTSTR + c)       = __floats2half2_rn(c00, c01);
            *(__half2*)(Ct + (r0 + 8) * CTSTR + c) = __floats2half2_rn(c10, c11);
        }
    }
    __syncthreads();

    const size_t base = (size_t)bz << 20;
    const int row = tid >> 1;
    const int off = (tid & 1) * 64;
    {   // C fp16 rows
#pragma unroll
        for (int u = 0; u < 8; u++) {
            uint4 q = *(const uint4*)(Ct + row * CTSTR + off + u * 8);
            *(uint4*)(d_C + base + (size_t)(n0 + row) * NPTS + m0 + off + u * 8) = q;
        }
    }
    {   // C8 uint8 rows
#pragma unroll
        for (int u = 0; u < 4; u++) {
            const __half* s = Ct + row * CTSTR + off + u * 16;
            uint4 q;
            unsigned w[4];
#pragma unroll
            for (int p = 0; p < 4; p++) {
                w[p] = (unsigned)q8(s[4 * p]) | ((unsigned)q8(s[4 * p + 1]) << 8) |
                       ((unsigned)q8(s[4 * p + 2]) << 16) | ((unsigned)q8(s[4 * p + 3]) << 24);
            }
            q.x = w[0]; q.y = w[1]; q.z = w[2]; q.w = w[3];
            *(uint4*)(d_C8 + base + (size_t)(n0 + row) * NPTS + m0 + off + u * 16) = q;
        }
    }

#pragma unroll
    for (int o = 16; o; o >>= 1) mx = fmaxf(mx, __shfl_xor_sync(0xffffffffu, mx, o));
    if (lane == 0) s_wmax[warp] = mx;
    __syncthreads();
    if (tid == 0) {
        float bm = s_wmax[0];
#pragma unroll
        for (int w = 1; w < 8; w++) bm = fmaxf(bm, s_wmax[w]);
        atomicMax(&d_maxbits, __float_as_uint(bm));
    }
}

// ---------------- persistent Sinkhorn: one barrier/iter, no C^T -------------
#define SK_GRID 128
#define SK_DSMEM 170768

// release/acquire barrier (cooperative-groups grid-sync pattern)
__device__ __forceinline__ void batch_barrier(int batch, unsigned target) {
    __syncthreads();
    if (threadIdx.x == 0) {
        unsigned* ctr = &d_bar[batch * 32];
        asm volatile("red.release.gpu.global.add.u32 [%0], %1;"
                     :: "l"(ctr), "r"(1u) : "memory");
        unsigned v;
        do {
            asm volatile("ld.acquire.gpu.global.u32 %0, [%1];"
                         : "=r"(v) : "l"(ctr) : "memory");
        } while (v < target);
    }
    __syncthreads();
}

__device__ __forceinline__ __half2 h2u(unsigned u) { return *(__half2*)&u; }

// uint8 row dot (row as 2 uint4 per lane-chunk) vs v chunks
__device__ __forceinline__ float dotrow_q(uint4 q0, uint4 q1,
                                          const uint4 va0, const uint4 va1,
                                          const uint4 vb0, const uint4 vb1) {
    const unsigned K = 0x64006400u;
    const __half2 k = *(const __half2*)&K;
    __half2 A = __floats2half2_rn(0.f, 0.f);
    __half2 B = A;
#define QW(w, v01, v23)                                                        \
    { unsigned rlo, rhi;                                                       \
      asm("prmt.b32 %0,%1,%2,0x5140;" : "=r"(rlo) : "r"(w), "r"(0x64646464u)); \
      asm("prmt.b32 %0,%1,%2,0x7362;" : "=r"(rhi) : "r"(w), "r"(0x64646464u)); \
      A = __hfma2(__hsub2(*(__half2*)&rlo, k), *(const __half2*)&(v01), A);    \
      B = __hfma2(__hsub2(*(__half2*)&rhi, k), *(const __half2*)&(v23), B); }
    QW(q0.x, va0.x, va0.y) QW(q0.y, va0.z, va0.w)
    QW(q0.z, va1.x, va1.y) QW(q0.w, va1.z, va1.w)
    QW(q1.x, vb0.x, vb0.y) QW(q1.y, vb0.z, vb0.w)
    QW(q1.z, vb1.x, vb1.y) QW(q1.w, vb1.z, vb1.w)
#undef QW
    return __low2float(A) + __high2float(A) + __low2float(B) + __high2float(B);
}

// 4 row dots from the padded smem slab (stride 65 uint4)
__device__ __forceinline__ void dot4q_s(const uint4* __restrict__ sw,
                                        const uint4* __restrict__ sv4, int lane,
                                        float& s0, float& s1, float& s2, float& s3) {
    const uint4 va0 = sv4[2 * lane], va1 = sv4[2 * lane + 1];
    const uint4 vb0 = sv4[64 + 2 * lane], vb1 = sv4[64 + 2 * lane + 1];
    s0 = dotrow_q(sw[lane],       sw[32 + lane],  va0, va1, vb0, vb1);
    s1 = dotrow_q(sw[65 + lane],  sw[97 + lane],  va0, va1, vb0, vb1);
    s2 = dotrow_q(sw[130 + lane], sw[162 + lane], va0, va1, vb0, vb1);
    s3 = dotrow_q(sw[195 + lane], sw[227 + lane], va0, va1, vb0, vb1);
}

// fp16 4-row dot from global C
__device__ __forceinline__ void dot4h(const __half* __restrict__ rowbase,
                                      const __half2* __restrict__ sv2, int lane,
                                      float& s0, float& s1, float& s2, float& s3) {
    const uint4* r = (const uint4*)rowbase;
    __half2 z = __floats2half2_rn(0.f, 0.f);
    __half2 a0a = z, a0b = z, a1a = z, a1b = z, a2a = z, a2b = z, a3a = z, a3b = z;
#pragma unroll
    for (int k = 0; k < 4; k++) {
        int idx = lane + 32 * k;
        uint4 vv = *(const uint4*)(sv2 + idx * 4);
        __half2 v0 = h2u(vv.x), v1 = h2u(vv.y), v2 = h2u(vv.z), v3 = h2u(vv.w);
        uint4 q0 = r[idx];
        uint4 q1 = r[idx + 128];
        uint4 q2 = r[idx + 256];
        uint4 q3 = r[idx + 384];
        a0a = __hfma2(h2u(q0.x), v0, a0a); a0b = __hfma2(h2u(q0.y), v1, a0b);
        a0a = __hfma2(h2u(q0.z), v2, a0a); a0b = __hfma2(h2u(q0.w), v3, a0b);
        a1a = __hfma2(h2u(q1.x), v0, a1a); a1b = __hfma2(h2u(q1.y), v1, a1b);
        a1a = __hfma2(h2u(q1.z), v2, a1a); a1b = __hfma2(h2u(q1.w), v3, a1b);
        a2a = __hfma2(h2u(q2.x), v0, a2a); a2b = __hfma2(h2u(q2.y), v1, a2b);
        a2a = __hfma2(h2u(q2.z), v2, a2a); a2b = __hfma2(h2u(q2.w), v3, a2b);
        a3a = __hfma2(h2u(q3.x), v0, a3a); a3b = __hfma2(h2u(q3.y), v1, a3b);
        a3a = __hfma2(h2u(q3.z), v2, a3a); a3b = __hfma2(h2u(q3.w), v3, a3b);
    }
    s0 = __low2float(a0a) + __high2float(a0a) + __low2float(a0b) + __high2float(a0b);
    s1 = __low2float(a1a) + __high2float(a1a) + __low2float(a1b) + __high2float(a1b);
    s2 = __low2float(a2a) + __high2float(a2a) + __low2float(a2b) + __high2float(a2b);
    s3 = __low2float(a3a) + __high2float(a3a) + __low2float(a3b) + __high2float(a3b);
}

#define WARP_RED4(s0, s1, s2, s3)                          \
    _Pragma("unroll")                                      \
    for (int o = 16; o; o >>= 1) {                         \
        s0 += __shfl_xor_sync(0xffffffffu, s0, o);         \
        s1 += __shfl_xor_sync(0xffffffffu, s1, o);         \
        s2 += __shfl_xor_sync(0xffffffffu, s2, o);         \
        s3 += __shfl_xor_sync(0xffffffffu, s3, o);         \
    }

// decode one uint (4 uint8 cols) and accumulate into 2 half2 col-accumulators
#define CDEC(w, aE, aO, u2, kb)                                                \
    { unsigned rlo, rhi;                                                       \
      asm("prmt.b32 %0,%1,%2,0x5140;" : "=r"(rlo) : "r"(w), "r"(0x64646464u)); \
      asm("prmt.b32 %0,%1,%2,0x7362;" : "=r"(rhi) : "r"(w), "r"(0x64646464u)); \
      aE = __hfma2(__hsub2(*(__half2*)&rlo, kb), u2, aE);                      \
      aO = __hfma2(__hsub2(*(__half2*)&rhi, kb), u2, aO); }

__global__ void __launch_bounds__(1024, 1)
sinkhorn_kernel(float* __restrict__ out) {
    extern __shared__ __align__(16) unsigned char sk[];
    uint4*   slab = (uint4*)sk;
    __half*  sv   = (__half*)(sk + 133120);
    __half*  suh  = (__half*)(sk + 135168);
    __half2* sred = (__half2*)(sk + 135936);
    float*   saux = (float*)(sk + 170752);

    const int tid   = threadIdx.x;
    const int warp  = tid >> 5;
    const int lane  = tid & 31;
    const int blk   = blockIdx.x;
    const int batch = blk >> 3;
    const int rank  = blk & 7;
    const int cg    = tid >> 4;     // column group (16 cols)
    const int rc    = tid & 15;     // row chunk

    // preload uint8 slab (128 rows, padded to 65 uint4 stride)
    {
        const uint4* src = (const uint4*)(d_C8 + ((size_t)batch << 20) + ((size_t)rank << 17));
#pragma unroll
        for (int j = 0; j < 8; j++) {
            int g = tid + 1024 * j;
            slab[(g >> 6) * 65 + (g & 63)] = src[g];
        }
    }
    sv[tid] = __float2half(1.0f / NPTS);
    if (tid == 0) saux[0] = 0.0f;

    const float invM = 1.0f / __uint_as_float(d_maxbits);
    const float qsc  = invM * (2.0f / 255.0f);
    float* vp_mine = d_vpart + (batch * 8 + rank) * NPTS;
    const float* vp_all = d_vpart + batch * 8 * NPTS;
    const unsigned KB = 0x64006400u;
    const __half2 kb = *(const __half2*)&KB;
    __syncthreads();

    unsigned step = 0;
    for (int iter = 0; iter < INT8_IT; iter++) {
        // ---- u (local rows, smem slab)
        float s0, s1, s2, s3;
        dot4q_s(slab + warp * 4 * 65, (const uint4*)sv, lane, s0, s1, s2, s3);
        WARP_RED4(s0, s1, s2, s3)
        if (lane < 4) {
            float s = (lane == 0) ? s0 : (lane == 1) ? s1 : (lane == 2) ? s2 : s3;
            float uv = 1.0f / (fmaf(qsc, s, EPS_SK));
            suh[warp * 4 + lane] = __float2half(uv);
        }
        __syncthreads();

        // ---- column partials from own slab (rows rc+16j, bank-safe)
        {
            __half2 z = __floats2half2_rn(0.f, 0.f);
            __half2 acc[8] = {z, z, z, z, z, z, z, z};
#pragma unroll
            for (int j = 0; j < 8; j++) {
                int r = rc + 16 * j;
                uint4 q = slab[r * 65 + cg];
                __half2 u2 = __half2half2(suh[r]);
                CDEC(q.x, acc[0], acc[1], u2, kb)
                CDEC(q.y, acc[2], acc[3], u2, kb)
                CDEC(q.z, acc[4], acc[5], u2, kb)
                CDEC(q.w, acc[6], acc[7], u2, kb)
            }
#pragma unroll
            for (int h = 0; h < 8; h++) sred[(cg * 8 + h) * 17 + rc] = acc[h];
        }
        __syncthreads();
        if (tid < 512) {
            const __half2* p = sred + tid * 17;
            float fx = 0.f, fy = 0.f;
#pragma unroll
            for (int k2 = 0; k2 < 16; k2++) {
                float2 f = __half22float2(p[k2]);
                fx += f.x; fy += f.y;
            }
            int m0 = 16 * (tid >> 3) + 2 * (tid & 7);
            float2 st; st.x = fx; st.y = fy;
            *(float2*)(vp_mine + m0) = st;
        }
        batch_barrier(batch, 8 * (++step));
        // ---- v recompute (identical in all blocks of the batch)
        {
            float a = 0.f;
#pragma unroll
            for (int k = 0; k < 8; k++) a += vp_all[k * NPTS + tid];
            sv[tid] = __float2half(1.0f / (fmaf(qsc, a, EPS_SK)));
        }
        __syncthreads();
    }

    // ---- polish iterations: same structure on fp16 C from global
    const __half* Cb = d_C + ((size_t)batch << 20) + ((size_t)rank << 17);
    float last_a = 0.0f;   // this thread's final column-sum (C^T u)_tid
    for (int iter = 0; iter < POLISH_IT; iter++) {
        float s0, s1, s2, s3;
        dot4h(Cb + (size_t)(warp * 4) * NPTS, (const __half2*)sv, lane, s0, s1, s2, s3);
        WARP_RED4(s0, s1, s2, s3)
        if (lane < 4) {
            float s = (lane == 0) ? s0 : (lane == 1) ? s1 : (lane == 2) ? s2 : s3;
            float uv = 1.0f / (fmaf(invM, s, EPS_SK));
            suh[warp * 4 + lane] = __float2half(uv);
        }
        __syncthreads();
        {
            __half2 z = __floats2half2_rn(0.f, 0.f);
            __half2 acc[8] = {z, z, z, z, z, z, z, z};
#pragma unroll
            for (int j = 0; j < 8; j++) {
                int r = rc + 16 * j;
                const uint4* gq = (const uint4*)(Cb + (size_t)r * NPTS) + 2 * cg;
                uint4 q0 = gq[0], q1 = gq[1];
                __half2 u2 = __half2half2(suh[r]);
                acc[0] = __hfma2(h2u(q0.x), u2, acc[0]);
                acc[1] = __hfma2(h2u(q0.y), u2, acc[1]);
                acc[2] = __hfma2(h2u(q0.z), u2, acc[2]);
                acc[3] = __hfma2(h2u(q0.w), u2, acc[3]);
                acc[4] = __hfma2(h2u(q1.x), u2, acc[4]);
                acc[5] = __hfma2(h2u(q1.y), u2, acc[5]);
                acc[6] = __hfma2(h2u(q1.z), u2, acc[6]);
                acc[7] = __hfma2(h2u(q1.w), u2, acc[7]);
            }
#pragma unroll
            for (int h = 0; h < 8; h++) sred[(cg * 8 + h) * 17 + rc] = acc[h];
        }
        __syncthreads();
        if (tid < 512) {
            const __half2* p = sred + tid * 17;
            float fx = 0.f, fy = 0.f;
#pragma unroll
            for (int k2 = 0; k2 < 16; k2++) {
                float2 f = __half22float2(p[k2]);
                fx += f.x; fy += f.y;
            }
            int m0 = 16 * (tid >> 3) + 2 * (tid & 7);
            float2 st; st.x = fx; st.y = fy;
            *(float2*)(vp_mine + m0) = st;
        }
        batch_barrier(batch, 8 * (++step));
        {
            float a = 0.f;
#pragma unroll
            for (int k = 0; k < 8; k++) a += vp_all[k * NPTS + tid];
            last_a = a;
            sv[tid] = __float2half(1.0f / (fmaf(invM, a, EPS_SK)));
        }
        __syncthreads();
    }

    // ---- distance = invM * Σ_j a_j v_j  (stationarity-fused final reduction)
    {
        float v  = 1.0f / (fmaf(invM, last_a, EPS_SK));
        float c  = invM * last_a * v;
#pragma unroll
        for (int o = 16; o; o >>= 1) c += __shfl_xor_sync(0xffffffffu, c, o);
        if (lane == 0) atomicAdd(&saux[0], c);
        __syncthreads();
        if (tid == 0 && rank == 0) atomicAdd(out, saux[0] * (1.0f / BATCHES));
    }
}

// ---------------- launch ----------------------------------------------------
extern "C" void kernel_launch(void* const* d_in, const int* in_sizes, int n_in,
                              void* d_out, int out_size) {
    (void)in_sizes; (void)n_in; (void)out_size;
    const float* x = (const float*)d_in[0];
    const float* y = (const float*)d_in[1];
    float* out = (float*)d_out;

    static int attr_set = 0;
    if (!attr_set) {
        cudaFuncSetAttribute(sinkhorn_kernel,
                             cudaFuncAttributeMaxDynamicSharedMemorySize, SK_DSMEM);
        cudaFuncSetAttribute(gemm_cost_mma,
                             cudaFuncAttributeMaxDynamicSharedMemorySize, GEMM_DSMEM);
        attr_set = 1;
    }

    normc_kernel<<<4096, 256>>>(x, y, out);
    dim3 g(8, 8, 16);
    gemm_cost_mma<<<g, 256, GEMM_DSMEM>>>();
    sinkhorn_kernel<<<SK_GRID, 1024, SK_DSMEM>>>(out);
}

// round 15
// speedup vs baseline: 2.2073x; 1.0879x over previous
#include <cuda_runtime.h>
#include <cuda_fp16.h>
#include <cstdint>

#define BATCHES 16
#define NPTS    1024
#define DIMS    1024
#define EPS_SK  1e-3f
#define INT8_IT    6
#define POLISH_IT  1

// ---------------- scratch (static device globals; no runtime alloc) --------
__device__ __half         d_C [BATCHES * NPTS * NPTS];   // fp16 C (polish, 32 MB)
__device__ unsigned char  d_C8[BATCHES * NPTS * NPTS];   // uint8 C = rn(255*C/2) (16 MB)
__device__ __half  d_xh[BATCHES * NPTS * DIMS];
__device__ __half  d_yh[BATCHES * NPTS * DIMS];
__device__ float   d_vpart[BATCHES * 8 * NPTS];          // per-rank column partials
__device__ unsigned d_maxbits;
__device__ unsigned d_bar[BATCHES * 32];                 // per-batch barrier ctrs

// ---------------- normalize rows -> fp16 (+ fused per-replay init) ----------
__global__ void normc_kernel(const float* __restrict__ x,
                             const float* __restrict__ y,
                             float* __restrict__ out) {
    if (blockIdx.x == 0) {
        for (int t = threadIdx.x; t < BATCHES * 32; t += blockDim.x) d_bar[t] = 0u;
        if (threadIdx.x == 0) { d_maxbits = 0u; out[0] = 0.0f; }
    }
    int gw   = blockIdx.x * 8 + (threadIdx.x >> 5);
    int lane = threadIdx.x & 31;
    const float* src;
    __half* dst;
    if (gw < BATCHES * NPTS) { src = x + (size_t)gw * DIMS;                     dst = d_xh + (size_t)gw * DIMS; }
    else                     { src = y + (size_t)(gw - BATCHES * NPTS) * DIMS;  dst = d_yh + (size_t)(gw - BATCHES * NPTS) * DIMS; }
    const float4* p = (const float4*)src;
    float4 f[8];
    float ss = 0.0f;
#pragma unroll
    for (int k = 0; k < 8; k++) {
        f[k] = p[lane + 32 * k];
        ss += f[k].x * f[k].x + f[k].y * f[k].y + f[k].z * f[k].z + f[k].w * f[k].w;
    }
#pragma unroll
    for (int o = 16; o; o >>= 1) ss += __shfl_xor_sync(0xffffffffu, ss, o);
    float inv = 1.0f / fmaxf(sqrtf(ss), 1e-12f);
#pragma unroll
    for (int k = 0; k < 8; k++) {
        __half2 h0 = __floats2half2_rn(f[k].x * inv, f[k].y * inv);
        __half2 h1 = __floats2half2_rn(f[k].z * inv, f[k].w * inv);
        uint2 u; u.x = *(unsigned*)&h0; u.y = *(unsigned*)&h1;
        *(uint2*)(dst + (size_t)(lane + 32 * k) * 4) = u;
    }
}

// ---------------- tensor-core cost GEMM (3-stage cp.async pipeline) ---------
#define SSTRIDE 40
#define CTSTR   136
#define GEMM_STG_B (128 * SSTRIDE * 2)            // 10240 B per stage buffer
#define GEMM_DSMEM (6 * GEMM_STG_B)               // 3 stages x (A,B) = 61440 B

#define CP_ASYNC16(saddr, gptr) \
    asm volatile("cp.async.cg.shared.global [%0], [%1], 16;" :: "r"(saddr), "l"(gptr))
#define CP_COMMIT() asm volatile("cp.async.commit_group;")
#define CP_WAIT0()  asm volatile("cp.async.wait_group 0;" ::: "memory")
#define CP_WAIT1()  asm volatile("cp.async.wait_group 1;" ::: "memory")

#define LDSM_X4(r0, r1, r2, r3, addr)                                          \
    asm volatile("ldmatrix.sync.aligned.m8n8.x4.shared.b16 {%0,%1,%2,%3}, [%4];" \
        : "=r"(r0), "=r"(r1), "=r"(r2), "=r"(r3) : "r"(addr))

__device__ __forceinline__ void mma16816(float* d, const unsigned* a, const unsigned* b) {
    asm volatile(
        "mma.sync.aligned.m16n8k16.row.col.f32.f16.f16.f32 "
        "{%0,%1,%2,%3}, {%4,%5,%6,%7}, {%8,%9}, {%0,%1,%2,%3};"
        : "+f"(d[0]), "+f"(d[1]), "+f"(d[2]), "+f"(d[3])
        : "r"(a[0]), "r"(a[1]), "r"(a[2]), "r"(a[3]), "r"(b[0]), "r"(b[1]));
}

__device__ __forceinline__ unsigned char q8(__half h) {
    return (unsigned char)__float2uint_rn(__saturatef(__half2float(h) * 0.5f) * 255.0f);
}

__global__ void __launch_bounds__(256, 2)
gemm_cost_mma(void) {
    extern __shared__ __align__(16) __half gsm[];   // 3-stage staging / epilogue Ct
    __shared__ float s_wmax[8];

    const int tid  = threadIdx.x;
    const int warp = tid >> 5;
    const int lane = tid & 31;
    const int wm   = warp >> 2;
    const int wn   = warp & 3;
    const int lq   = lane >> 2;
    const int lr4  = lane & 3;
    const int bz   = blockIdx.z;
    const int n0   = blockIdx.y * 128;
    const int m0   = blockIdx.x * 128;

    const __half* xb = d_xh + ((size_t)bz << 20);
    const __half* yb = d_yh + ((size_t)bz << 20);

    const int lrow = tid >> 2;
    const int lseg = tid & 3;
    const __half* gxa = xb + (size_t)(n0 + lrow) * DIMS + lseg * 8;
    const __half* gxb = xb + (size_t)(n0 + lrow + 64) * DIMS + lseg * 8;
    const __half* gya = yb + (size_t)(m0 + lrow) * DIMS + lseg * 8;
    const __half* gyb = yb + (size_t)(m0 + lrow + 64) * DIMS + lseg * 8;

    const uint32_t smem_u32 = (uint32_t)__cvta_generic_to_shared(gsm);
    const uint32_t STG = (uint32_t)GEMM_STG_B;
    const uint32_t BBASE = 3u * STG;                 // B region after 3 A stages
    const uint32_t sAa = smem_u32 + 2u * (lrow * SSTRIDE + lseg * 8);
    const uint32_t sAb = smem_u32 + 2u * ((lrow + 64) * SSTRIDE + lseg * 8);
    const uint32_t sBa = smem_u32 + BBASE + 2u * (lrow * SSTRIDE + lseg * 8);
    const uint32_t sBb = smem_u32 + BBASE + 2u * ((lrow + 64) * SSTRIDE + lseg * 8);

#define LOAD_STAGE(stg, k0)                                   \
    { CP_ASYNC16(sAa + (stg) * STG, gxa + (k0));              \
      CP_ASYNC16(sAb + (stg) * STG, gxb + (k0));              \
      CP_ASYNC16(sBa + (stg) * STG, gya + (k0));              \
      CP_ASYNC16(sBb + (stg) * STG, gyb + (k0));              \
      CP_COMMIT(); }

    const int arow_l = (lane & 7) + ((lane >> 3) & 1) * 8;
    const int acol_l = (lane >> 4) * 8;
    const int brow_l = lane & 7;
    const int bcol_l = ((lane >> 3) & 1) * 8;
    const int bjoff_l = (lane >> 4) * 8;     // x4 B: lanes 16-31 -> next j-tile

    float acc[4][4][4];
#pragma unroll
    for (int i = 0; i < 4; i++)
#pragma unroll
        for (int j = 0; j < 4; j++)
#pragma unroll
            for (int q = 0; q < 4; q++) acc[i][j][q] = 0.0f;

    LOAD_STAGE(0u, 0);
    LOAD_STAGE(1u, 32);

    unsigned stg = 0;   // buffer index of current k-iter (it % 3)
    for (int it = 0; it < 32; it++) {
        if (it < 31) CP_WAIT1(); else CP_WAIT0();
        __syncthreads();
        if (it < 30) {
            unsigned nstg = stg + 2; if (nstg >= 3) nstg -= 3;
            LOAD_STAGE(nstg, (it + 2) * 32);
        }
        const uint32_t aS = smem_u32 + stg * STG;
        const uint32_t bS = smem_u32 + BBASE + stg * STG;
#pragma unroll
        for (int ks = 0; ks < 32; ks += 16) {
            unsigned a[4][4], b[4][2];
#pragma unroll
            for (int i = 0; i < 4; i++) {
                uint32_t ad = aS + 2u * ((wm * 64 + i * 16 + arow_l) * SSTRIDE + ks + acol_l);
                LDSM_X4(a[i][0], a[i][1], a[i][2], a[i][3], ad);
            }
#pragma unroll
            for (int j = 0; j < 4; j += 2) {
                // x4 B load: lanes 0-15 address tile j (cols ks, ks+8),
                // lanes 16-31 address tile j+1 -> regs r2,r3.
                uint32_t bd = bS + 2u * ((wn * 32 + j * 8 + bjoff_l + brow_l) * SSTRIDE + ks + bcol_l);
                LDSM_X4(b[j][0], b[j][1], b[j + 1][0], b[j + 1][1], bd);
            }
#pragma unroll
            for (int i = 0; i < 4; i++)
#pragma unroll
                for (int j = 0; j < 4; j++) mma16816(acc[i][j], a[i], b[j]);
        }
        stg = (stg == 2) ? 0u : stg + 1u;
    }
    __syncthreads();
#undef LOAD_STAGE

    // epilogue: cost = 1 - dot; stage fp16 tile, write C fp16 + C8 uint8
    __half* Ct = gsm;   // 128 x CTSTR halves = 34816 B < GEMM_DSMEM
    float mx = 0.0f;
#pragma unroll
    for (int i = 0; i < 4; i++) {
        const int r0 = wm * 64 + i * 16 + lq;
#pragma unroll
        for (int j = 0; j < 4; j++) {
            const int c = wn * 32 + j * 8 + lr4 * 2;
            float c00 = 1.0f - acc[i][j][0];
            float c01 = 1.0f - acc[i][j][1];
            float c10 = 1.0f - acc[i][j][2];
            float c11 = 1.0f - acc[i][j][3];
            mx = fmaxf(mx, fmaxf(fmaxf(c00, c01), fmaxf(c10, c11)));
            *(__half2*)(Ct + r0 * CTSTR + c)       = __floats2half2_rn(c00, c01);
            *(__half2*)(Ct + (r0 + 8) * CTSTR + c) = __floats2half2_rn(c10, c11);
        }
    }
    __syncthreads();

    const size_t base = (size_t)bz << 20;
    const int row = tid >> 1;
    const int off = (tid & 1) * 64;
    {   // C fp16 rows
#pragma unroll
        for (int u = 0; u < 8; u++) {
            uint4 q = *(const uint4*)(Ct + row * CTSTR + off + u * 8);
            *(uint4*)(d_C + base + (size_t)(n0 + row) * NPTS + m0 + off + u * 8) = q;
        }
    }
    {   // C8 uint8 rows
#pragma unroll
        for (int u = 0; u < 4; u++) {
            const __half* s = Ct + row * CTSTR + off + u * 16;
            uint4 q;
            unsigned w[4];
#pragma unroll
            for (int p = 0; p < 4; p++) {
                w[p] = (unsigned)q8(s[4 * p]) | ((unsigned)q8(s[4 * p + 1]) << 8) |
                       ((unsigned)q8(s[4 * p + 2]) << 16) | ((unsigned)q8(s[4 * p + 3]) << 24);
            }
            q.x = w[0]; q.y = w[1]; q.z = w[2]; q.w = w[3];
            *(uint4*)(d_C8 + base + (size_t)(n0 + row) * NPTS + m0 + off + u * 16) = q;
        }
    }

#pragma unroll
    for (int o = 16; o; o >>= 1) mx = fmaxf(mx, __shfl_xor_sync(0xffffffffu, mx, o));
    if (lane == 0) s_wmax[warp] = mx;
    __syncthreads();
    if (tid == 0) {
        float bm = s_wmax[0];
#pragma unroll
        for (int w = 1; w < 8; w++) bm = fmaxf(bm, s_wmax[w]);
        atomicMax(&d_maxbits, __float_as_uint(bm));
    }
}

// ---------------- persistent Sinkhorn: one barrier/iter, no C^T -------------
#define SK_GRID 128
#define SK_DSMEM 170768

// release/acquire barrier (cooperative-groups grid-sync pattern)
__device__ __forceinline__ void batch_barrier(int batch, unsigned target) {
    __syncthreads();
    if (threadIdx.x == 0) {
        unsigned* ctr = &d_bar[batch * 32];
        asm volatile("red.release.gpu.global.add.u32 [%0], %1;"
                     :: "l"(ctr), "r"(1u) : "memory");
        unsigned v;
        do {
            asm volatile("ld.acquire.gpu.global.u32 %0, [%1];"
                         : "=r"(v) : "l"(ctr) : "memory");
        } while (v < target);
    }
    __syncthreads();
}

__device__ __forceinline__ __half2 h2u(unsigned u) { return *(__half2*)&u; }

// uint8 row dot (row as 2 uint4 per lane-chunk) vs v chunks
__device__ __forceinline__ float dotrow_q(uint4 q0, uint4 q1,
                                          const uint4 va0, const uint4 va1,
                                          const uint4 vb0, const uint4 vb1) {
    const unsigned K = 0x64006400u;
    const __half2 k = *(const __half2*)&K;
    __half2 A = __floats2half2_rn(0.f, 0.f);
    __half2 B = A;
#define QW(w, v01, v23)                                                        \
    { unsigned rlo, rhi;                                                       \
      asm("prmt.b32 %0,%1,%2,0x5140;" : "=r"(rlo) : "r"(w), "r"(0x64646464u)); \
      asm("prmt.b32 %0,%1,%2,0x7362;" : "=r"(rhi) : "r"(w), "r"(0x64646464u)); \
      A = __hfma2(__hsub2(*(__half2*)&rlo, k), *(const __half2*)&(v01), A);    \
      B = __hfma2(__hsub2(*(__half2*)&rhi, k), *(const __half2*)&(v23), B); }
    QW(q0.x, va0.x, va0.y) QW(q0.y, va0.z, va0.w)
    QW(q0.z, va1.x, va1.y) QW(q0.w, va1.z, va1.w)
    QW(q1.x, vb0.x, vb0.y) QW(q1.y, vb0.z, vb0.w)
    QW(q1.z, vb1.x, vb1.y) QW(q1.w, vb1.z, vb1.w)
#undef QW
    return __low2float(A) + __high2float(A) + __low2float(B) + __high2float(B);
}

// 4 row dots from the padded smem slab (stride 65 uint4)
__device__ __forceinline__ void dot4q_s(const uint4* __restrict__ sw,
                                        const uint4* __restrict__ sv4, int lane,
                                        float& s0, float& s1, float& s2, float& s3) {
    const uint4 va0 = sv4[2 * lane], va1 = sv4[2 * lane + 1];
    const uint4 vb0 = sv4[64 + 2 * lane], vb1 = sv4[64 + 2 * lane + 1];
    s0 = dotrow_q(sw[lane],       sw[32 + lane],  va0, va1, vb0, vb1);
    s1 = dotrow_q(sw[65 + lane],  sw[97 + lane],  va0, va1, vb0, vb1);
    s2 = dotrow_q(sw[130 + lane], sw[162 + lane], va0, va1, vb0, vb1);
    s3 = dotrow_q(sw[195 + lane], sw[227 + lane], va0, va1, vb0, vb1);
}

// fp16 4-row dot from global C
__device__ __forceinline__ void dot4h(const __half* __restrict__ rowbase,
                                      const __half2* __restrict__ sv2, int lane,
                                      float& s0, float& s1, float& s2, float& s3) {
    const uint4* r = (const uint4*)rowbase;
    __half2 z = __floats2half2_rn(0.f, 0.f);
    __half2 a0a = z, a0b = z, a1a = z, a1b = z, a2a = z, a2b = z, a3a = z, a3b = z;
#pragma unroll
    for (int k = 0; k < 4; k++) {
        int idx = lane + 32 * k;
        uint4 vv = *(const uint4*)(sv2 + idx * 4);
        __half2 v0 = h2u(vv.x), v1 = h2u(vv.y), v2 = h2u(vv.z), v3 = h2u(vv.w);
        uint4 q0 = r[idx];
        uint4 q1 = r[idx + 128];
        uint4 q2 = r[idx + 256];
        uint4 q3 = r[idx + 384];
        a0a = __hfma2(h2u(q0.x), v0, a0a); a0b = __hfma2(h2u(q0.y), v1, a0b);
        a0a = __hfma2(h2u(q0.z), v2, a0a); a0b = __hfma2(h2u(q0.w), v3, a0b);
        a1a = __hfma2(h2u(q1.x), v0, a1a); a1b = __hfma2(h2u(q1.y), v1, a1b);
        a1a = __hfma2(h2u(q1.z), v2, a1a); a1b = __hfma2(h2u(q1.w), v3, a1b);
        a2a = __hfma2(h2u(q2.x), v0, a2a); a2b = __hfma2(h2u(q2.y), v1, a2b);
        a2a = __hfma2(h2u(q2.z), v2, a2a); a2b = __hfma2(h2u(q2.w), v3, a2b);
        a3a = __hfma2(h2u(q3.x), v0, a3a); a3b = __hfma2(h2u(q3.y), v1, a3b);
        a3a = __hfma2(h2u(q3.z), v2, a3a); a3b = __hfma2(h2u(q3.w), v3, a3b);
    }
    s0 = __low2float(a0a) + __high2float(a0a) + __low2float(a0b) + __high2float(a0b);
    s1 = __low2float(a1a) + __high2float(a1a) + __low2float(a1b) + __high2float(a1b);
    s2 = __low2float(a2a) + __high2float(a2a) + __low2float(a2b) + __high2float(a2b);
    s3 = __low2float(a3a) + __high2float(a3a) + __low2float(a3b) + __high2float(a3b);
}

#define WARP_RED4(s0, s1, s2, s3)                          \
    _Pragma("unroll")                                      \
    for (int o = 16; o; o >>= 1) {                         \
        s0 += __shfl_xor_sync(0xffffffffu, s0, o);         \
        s1 += __shfl_xor_sync(0xffffffffu, s1, o);         \
        s2 += __shfl_xor_sync(0xffffffffu, s2, o);         \
        s3 += __shfl_xor_sync(0xffffffffu, s3, o);         \
    }

// decode one uint (4 uint8 cols) and accumulate into 2 half2 col-accumulators
#define CDEC(w, aE, aO, u2, kb)                                                \
    { unsigned rlo, rhi;                                                       \
      asm("prmt.b32 %0,%1,%2,0x5140;" : "=r"(rlo) : "r"(w), "r"(0x64646464u)); \
      asm("prmt.b32 %0,%1,%2,0x7362;" : "=r"(rhi) : "r"(w), "r"(0x64646464u)); \
      aE = __hfma2(__hsub2(*(__half2*)&rlo, kb), u2, aE);                      \
      aO = __hfma2(__hsub2(*(__half2*)&rhi, kb), u2, aO); }

__global__ void __launch_bounds__(1024, 1)
sinkhorn_kernel(float* __restrict__ out) {
    extern __shared__ __align__(16) unsigned char sk[];
    uint4*   slab = (uint4*)sk;
    __half*  sv   = (__half*)(sk + 133120);
    __half*  suh  = (__half*)(sk + 135168);
    __half2* sred = (__half2*)(sk + 135936);
    float*   saux = (float*)(sk + 170752);

    const int tid   = threadIdx.x;
    const int warp  = tid >> 5;
    const int lane  = tid & 31;
    const int blk   = blockIdx.x;
    const int batch = blk >> 3;
    const int rank  = blk & 7;
    const int cg    = tid >> 4;     // column group (16 cols)
    const int rc    = tid & 15;     // row chunk

    // preload uint8 slab (128 rows, padded to 65 uint4 stride)
    {
        const uint4* src = (const uint4*)(d_C8 + ((size_t)batch << 20) + ((size_t)rank << 17));
#pragma unroll
        for (int j = 0; j < 8; j++) {
            int g = tid + 1024 * j;
            slab[(g >> 6) * 65 + (g & 63)] = src[g];
        }
    }
    sv[tid] = __float2half(1.0f / NPTS);
    if (tid == 0) saux[0] = 0.0f;

    const float invM = 1.0f / __uint_as_float(d_maxbits);
    const float qsc  = invM * (2.0f / 255.0f);
    float* vp_mine = d_vpart + (batch * 8 + rank) * NPTS;
    const float* vp_all = d_vpart + batch * 8 * NPTS;
    const unsigned KB = 0x64006400u;
    const __half2 kb = *(const __half2*)&KB;
    __syncthreads();

    unsigned step = 0;
    for (int iter = 0; iter < INT8_IT; iter++) {
        // ---- u (local rows, smem slab)
        float s0, s1, s2, s3;
        dot4q_s(slab + warp * 4 * 65, (const uint4*)sv, lane, s0, s1, s2, s3);
        WARP_RED4(s0, s1, s2, s3)
        if (lane < 4) {
            float s = (lane == 0) ? s0 : (lane == 1) ? s1 : (lane == 2) ? s2 : s3;
            float uv = 1.0f / (fmaf(qsc, s, EPS_SK));
            suh[warp * 4 + lane] = __float2half(uv);
        }
        __syncthreads();

        // ---- column partials from own slab (rows rc+16j, bank-safe)
        {
            __half2 z = __floats2half2_rn(0.f, 0.f);
            __half2 acc[8] = {z, z, z, z, z, z, z, z};
#pragma unroll
            for (int j = 0; j < 8; j++) {
                int r = rc + 16 * j;
                uint4 q = slab[r * 65 + cg];
                __half2 u2 = __half2half2(suh[r]);
                CDEC(q.x, acc[0], acc[1], u2, kb)
                CDEC(q.y, acc[2], acc[3], u2, kb)
                CDEC(q.z, acc[4], acc[5], u2, kb)
                CDEC(q.w, acc[6], acc[7], u2, kb)
            }
#pragma unroll
            for (int h = 0; h < 8; h++) sred[(cg * 8 + h) * 17 + rc] = acc[h];
        }
        __syncthreads();
        if (tid < 512) {
            const __half2* p = sred + tid * 17;
            float fx = 0.f, fy = 0.f;
#pragma unroll
            for (int k2 = 0; k2 < 16; k2++) {
                float2 f = __half22float2(p[k2]);
                fx += f.x; fy += f.y;
            }
            int m0 = 16 * (tid >> 3) + 2 * (tid & 7);
            float2 st; st.x = fx; st.y = fy;
            *(float2*)(vp_mine + m0) = st;
        }
        batch_barrier(batch, 8 * (++step));
        // ---- v recompute (identical in all blocks of the batch)
        {
            float a = 0.f;
#pragma unroll
            for (int k = 0; k < 8; k++) a += vp_all[k * NPTS + tid];
            sv[tid] = __float2half(1.0f / (fmaf(qsc, a, EPS_SK)));
        }
        __syncthreads();
    }

    // ---- polish iteration(s): same structure on fp16 C from global
    const __half* Cb = d_C + ((size_t)batch << 20) + ((size_t)rank << 17);
    float last_a = 0.0f;   // this thread's final column-sum (C^T u)_tid
    for (int iter = 0; iter < POLISH_IT; iter++) {
        float s0, s1, s2, s3;
        dot4h(Cb + (size_t)(warp * 4) * NPTS, (const __half2*)sv, lane, s0, s1, s2, s3);
        WARP_RED4(s0, s1, s2, s3)
        if (lane < 4) {
            float s = (lane == 0) ? s0 : (lane == 1) ? s1 : (lane == 2) ? s2 : s3;
            float uv = 1.0f / (fmaf(invM, s, EPS_SK));
            suh[warp * 4 + lane] = __float2half(uv);
        }
        __syncthreads();
        {
            __half2 z = __floats2half2_rn(0.f, 0.f);
            __half2 acc[8] = {z, z, z, z, z, z, z, z};
#pragma unroll
            for (int j = 0; j < 8; j++) {
                int r = rc + 16 * j;
                const uint4* gq = (const uint4*)(Cb + (size_t)r * NPTS) + 2 * cg;
                uint4 q0 = gq[0], q1 = gq[1];
                __half2 u2 = __half2half2(suh[r]);
                acc[0] = __hfma2(h2u(q0.x), u2, acc[0]);
                acc[1] = __hfma2(h2u(q0.y), u2, acc[1]);
                acc[2] = __hfma2(h2u(q0.z), u2, acc[2]);
                acc[3] = __hfma2(h2u(q0.w), u2, acc[3]);
                acc[4] = __hfma2(h2u(q1.x), u2, acc[4]);
                acc[5] = __hfma2(h2u(q1.y), u2, acc[5]);
                acc[6] = __hfma2(h2u(q1.z), u2, acc[6]);
                acc[7] = __hfma2(h2u(q1.w), u2, acc[7]);
            }
#pragma unroll
            for (int h = 0; h < 8; h++) sred[(cg * 8 + h) * 17 + rc] = acc[h];
        }
        __syncthreads();
        if (tid < 512) {
            const __half2* p = sred + tid * 17;
            float fx = 0.f, fy = 0.f;
#pragma unroll
            for (int k2 = 0; k2 < 16; k2++) {
                float2 f = __half22float2(p[k2]);
                fx += f.x; fy += f.y;
            }
            int m0 = 16 * (tid >> 3) + 2 * (tid & 7);
            float2 st; st.x = fx; st.y = fy;
            *(float2*)(vp_mine + m0) = st;
        }
        batch_barrier(batch, 8 * (++step));
        {
            float a = 0.f;
#pragma unroll
            for (int k = 0; k < 8; k++) a += vp_all[k * NPTS + tid];
            last_a = a;
            sv[tid] = __float2half(1.0f / (fmaf(invM, a, EPS_SK)));
        }
        __syncthreads();
    }

    // ---- distance = invM * Σ_j a_j v_j  (stationarity-fused final reduction)
    {
        float v  = 1.0f / (fmaf(invM, last_a, EPS_SK));
        float c  = invM * last_a * v;
#pragma unroll
        for (int o = 16; o; o >>= 1) c += __shfl_xor_sync(0xffffffffu, c, o);
        if (lane == 0) atomicAdd(&saux[0], c);
        __syncthreads();
        if (tid == 0 && rank == 0) atomicAdd(out, saux[0] * (1.0f / BATCHES));
    }
}

// ---------------- launch ----------------------------------------------------
extern "C" void kernel_launch(void* const* d_in, const int* in_sizes, int n_in,
                              void* d_out, int out_size) {
    (void)in_sizes; (void)n_in; (void)out_size;
    const float* x = (const float*)d_in[0];
    const float* y = (const float*)d_in[1];
    float* out = (float*)d_out;

    static int attr_set = 0;
    if (!attr_set) {
        cudaFuncSetAttribute(sinkhorn_kernel,
                             cudaFuncAttributeMaxDynamicSharedMemorySize, SK_DSMEM);
        cudaFuncSetAttribute(gemm_cost_mma,
                             cudaFuncAttributeMaxDynamicSharedMemorySize, GEMM_DSMEM);
        attr_set = 1;
    }

    normc_kernel<<<4096, 256>>>(x, y, out);
    dim3 g(8, 8, 16);
    gemm_cost_mma<<<g, 256, GEMM_DSMEM>>>();
    sinkhorn_kernel<<<SK_GRID, 1024, SK_DSMEM>>>(out);
}

// round 16
// speedup vs baseline: 2.3149x; 1.0487x over previous
#include <cuda_runtime.h>
#include <cuda_fp16.h>
#include <cstdint>

#define BATCHES 16
#define NPTS    1024
#define DIMS    1024
#define EPS_SK  1e-3f
#define INT8_IT    4
#define POLISH_IT  1

// ---------------- scratch (static device globals; no runtime alloc) --------
__device__ __half         d_C [BATCHES * NPTS * NPTS];   // fp16 C (polish, 32 MB)
__device__ unsigned char  d_C8[BATCHES * NPTS * NPTS];   // uint8 C = rn(255*C/2) (16 MB)
__device__ __half  d_xh[BATCHES * NPTS * DIMS];
__device__ __half  d_yh[BATCHES * NPTS * DIMS];
__device__ float   d_vpart[BATCHES * 8 * NPTS];          // per-rank column partials
__device__ unsigned d_maxbits;
__device__ unsigned d_bar[BATCHES * 32];                 // per-batch barrier ctrs

// ---------------- normalize rows -> fp16 (+ fused per-replay init) ----------
__global__ void normc_kernel(const float* __restrict__ x,
                             const float* __restrict__ y,
                             float* __restrict__ out) {
    if (blockIdx.x == 0) {
        for (int t = threadIdx.x; t < BATCHES * 32; t += blockDim.x) d_bar[t] = 0u;
        if (threadIdx.x == 0) { d_maxbits = 0u; out[0] = 0.0f; }
    }
    int gw   = blockIdx.x * 8 + (threadIdx.x >> 5);
    int lane = threadIdx.x & 31;
    const float* src;
    __half* dst;
    if (gw < BATCHES * NPTS) { src = x + (size_t)gw * DIMS;                     dst = d_xh + (size_t)gw * DIMS; }
    else                     { src = y + (size_t)(gw - BATCHES * NPTS) * DIMS;  dst = d_yh + (size_t)(gw - BATCHES * NPTS) * DIMS; }
    const float4* p = (const float4*)src;
    float4 f[8];
    float ss = 0.0f;
#pragma unroll
    for (int k = 0; k < 8; k++) {
        f[k] = p[lane + 32 * k];
        ss += f[k].x * f[k].x + f[k].y * f[k].y + f[k].z * f[k].z + f[k].w * f[k].w;
    }
#pragma unroll
    for (int o = 16; o; o >>= 1) ss += __shfl_xor_sync(0xffffffffu, ss, o);
    float inv = 1.0f / fmaxf(sqrtf(ss), 1e-12f);
#pragma unroll
    for (int k = 0; k < 8; k++) {
        __half2 h0 = __floats2half2_rn(f[k].x * inv, f[k].y * inv);
        __half2 h1 = __floats2half2_rn(f[k].z * inv, f[k].w * inv);
        uint2 u; u.x = *(unsigned*)&h0; u.y = *(unsigned*)&h1;
        *(uint2*)(dst + (size_t)(lane + 32 * k) * 4) = u;
    }
}

// ---------------- tensor-core cost GEMM (3-stage cp.async pipeline) ---------
#define SSTRIDE 40
#define CTSTR   136
#define GEMM_STG_B (128 * SSTRIDE * 2)            // 10240 B per stage buffer
#define GEMM_DSMEM (6 * GEMM_STG_B)               // 3 stages x (A,B) = 61440 B

#define CP_ASYNC16(saddr, gptr) \
    asm volatile("cp.async.cg.shared.global [%0], [%1], 16;" :: "r"(saddr), "l"(gptr))
#define CP_COMMIT() asm volatile("cp.async.commit_group;")
#define CP_WAIT0()  asm volatile("cp.async.wait_group 0;" ::: "memory")
#define CP_WAIT1()  asm volatile("cp.async.wait_group 1;" ::: "memory")

#define LDSM_X4(r0, r1, r2, r3, addr)                                          \
    asm volatile("ldmatrix.sync.aligned.m8n8.x4.shared.b16 {%0,%1,%2,%3}, [%4];" \
        : "=r"(r0), "=r"(r1), "=r"(r2), "=r"(r3) : "r"(addr))

__device__ __forceinline__ void mma16816(float* d, const unsigned* a, const unsigned* b) {
    asm volatile(
        "mma.sync.aligned.m16n8k16.row.col.f32.f16.f16.f32 "
        "{%0,%1,%2,%3}, {%4,%5,%6,%7}, {%8,%9}, {%0,%1,%2,%3};"
        : "+f"(d[0]), "+f"(d[1]), "+f"(d[2]), "+f"(d[3])
        : "r"(a[0]), "r"(a[1]), "r"(a[2]), "r"(a[3]), "r"(b[0]), "r"(b[1]));
}

__device__ __forceinline__ unsigned char q8(__half h) {
    return (unsigned char)__float2uint_rn(__saturatef(__half2float(h) * 0.5f) * 255.0f);
}

__global__ void __launch_bounds__(256, 2)
gemm_cost_mma(void) {
    extern __shared__ __align__(16) __half gsm[];   // 3-stage staging / epilogue Ct
    __shared__ float s_wmax[8];

    const int tid  = threadIdx.x;
    const int warp = tid >> 5;
    const int lane = tid & 31;
    const int wm   = warp >> 2;
    const int wn   = warp & 3;
    const int lq   = lane >> 2;
    const int lr4  = lane & 3;
    const int bz   = blockIdx.z;
    const int n0   = blockIdx.y * 128;
    const int m0   = blockIdx.x * 128;

    const __half* xb = d_xh + ((size_t)bz << 20);
    const __half* yb = d_yh + ((size_t)bz << 20);

    const int lrow = tid >> 2;
    const int lseg = tid & 3;
    const __half* gxa = xb + (size_t)(n0 + lrow) * DIMS + lseg * 8;
    const __half* gxb = xb + (size_t)(n0 + lrow + 64) * DIMS + lseg * 8;
    const __half* gya = yb + (size_t)(m0 + lrow) * DIMS + lseg * 8;
    const __half* gyb = yb + (size_t)(m0 + lrow + 64) * DIMS + lseg * 8;

    const uint32_t smem_u32 = (uint32_t)__cvta_generic_to_shared(gsm);
    const uint32_t STG = (uint32_t)GEMM_STG_B;
    const uint32_t BBASE = 3u * STG;                 // B region after 3 A stages
    const uint32_t sAa = smem_u32 + 2u * (lrow * SSTRIDE + lseg * 8);
    const uint32_t sAb = smem_u32 + 2u * ((lrow + 64) * SSTRIDE + lseg * 8);
    const uint32_t sBa = smem_u32 + BBASE + 2u * (lrow * SSTRIDE + lseg * 8);
    const uint32_t sBb = smem_u32 + BBASE + 2u * ((lrow + 64) * SSTRIDE + lseg * 8);

#define LOAD_STAGE(stg, k0)                                   \
    { CP_ASYNC16(sAa + (stg) * STG, gxa + (k0));              \
      CP_ASYNC16(sAb + (stg) * STG, gxb + (k0));              \
      CP_ASYNC16(sBa + (stg) * STG, gya + (k0));              \
      CP_ASYNC16(sBb + (stg) * STG, gyb + (k0));              \
      CP_COMMIT(); }

    const int arow_l = (lane & 7) + ((lane >> 3) & 1) * 8;
    const int acol_l = (lane >> 4) * 8;
    const int brow_l = lane & 7;
    const int bcol_l = ((lane >> 3) & 1) * 8;
    const int bjoff_l = (lane >> 4) * 8;     // x4 B: lanes 16-31 -> next j-tile

    float acc[4][4][4];
#pragma unroll
    for (int i = 0; i < 4; i++)
#pragma unroll
        for (int j = 0; j < 4; j++)
#pragma unroll
            for (int q = 0; q < 4; q++) acc[i][j][q] = 0.0f;

    LOAD_STAGE(0u, 0);
    LOAD_STAGE(1u, 32);

    unsigned stg = 0;   // buffer index of current k-iter (it % 3)
    for (int it = 0; it < 32; it++) {
        if (it < 31) CP_WAIT1(); else CP_WAIT0();
        __syncthreads();
        if (it < 30) {
            unsigned nstg = stg + 2; if (nstg >= 3) nstg -= 3;
            LOAD_STAGE(nstg, (it + 2) * 32);
        }
        const uint32_t aS = smem_u32 + stg * STG;
        const uint32_t bS = smem_u32 + BBASE + stg * STG;
#pragma unroll
        for (int ks = 0; ks < 32; ks += 16) {
            unsigned a[4][4], b[4][2];
#pragma unroll
            for (int i = 0; i < 4; i++) {
                uint32_t ad = aS + 2u * ((wm * 64 + i * 16 + arow_l) * SSTRIDE + ks + acol_l);
                LDSM_X4(a[i][0], a[i][1], a[i][2], a[i][3], ad);
            }
#pragma unroll
            for (int j = 0; j < 4; j += 2) {
                uint32_t bd = bS + 2u * ((wn * 32 + j * 8 + bjoff_l + brow_l) * SSTRIDE + ks + bcol_l);
                LDSM_X4(b[j][0], b[j][1], b[j + 1][0], b[j + 1][1], bd);
            }
#pragma unroll
            for (int i = 0; i < 4; i++)
#pragma unroll
                for (int j = 0; j < 4; j++) mma16816(acc[i][j], a[i], b[j]);
        }
        stg = (stg == 2) ? 0u : stg + 1u;
    }
    __syncthreads();
#undef LOAD_STAGE

    // epilogue: cost = 1 - dot; stage fp16 tile, write C fp16 + C8 uint8
    __half* Ct = gsm;   // 128 x CTSTR halves = 34816 B < GEMM_DSMEM
    float mx = 0.0f;
#pragma unroll
    for (int i = 0; i < 4; i++) {
        const int r0 = wm * 64 + i * 16 + lq;
#pragma unroll
        for (int j = 0; j < 4; j++) {
            const int c = wn * 32 + j * 8 + lr4 * 2;
            float c00 = 1.0f - acc[i][j][0];
            float c01 = 1.0f - acc[i][j][1];
            float c10 = 1.0f - acc[i][j][2];
            float c11 = 1.0f - acc[i][j][3];
            mx = fmaxf(mx, fmaxf(fmaxf(c00, c01), fmaxf(c10, c11)));
            *(__half2*)(Ct + r0 * CTSTR + c)       = __floats2half2_rn(c00, c01);
            *(__half2*)(Ct + (r0 + 8) * CTSTR + c) = __floats2half2_rn(c10, c11);
        }
    }
    __syncthreads();

    const size_t base = (size_t)bz << 20;
    const int row = tid >> 1;
    const int off = (tid & 1) * 64;
    {   // C fp16 rows
#pragma unroll
        for (int u = 0; u < 8; u++) {
            uint4 q = *(const uint4*)(Ct + row * CTSTR + off + u * 8);
            *(uint4*)(d_C + base + (size_t)(n0 + row) * NPTS + m0 + off + u * 8) = q;
        }
    }
    {   // C8 uint8 rows
#pragma unroll
        for (int u = 0; u < 4; u++) {
            const __half* s = Ct + row * CTSTR + off + u * 16;
            uint4 q;
            unsigned w[4];
#pragma unroll
            for (int p = 0; p < 4; p++) {
                w[p] = (unsigned)q8(s[4 * p]) | ((unsigned)q8(s[4 * p + 1]) << 8) |
                       ((unsigned)q8(s[4 * p + 2]) << 16) | ((unsigned)q8(s[4 * p + 3]) << 24);
            }
            q.x = w[0]; q.y = w[1]; q.z = w[2]; q.w = w[3];
            *(uint4*)(d_C8 + base + (size_t)(n0 + row) * NPTS + m0 + off + u * 16) = q;
        }
    }

#pragma unroll
    for (int o = 16; o; o >>= 1) mx = fmaxf(mx, __shfl_xor_sync(0xffffffffu, mx, o));
    if (lane == 0) s_wmax[warp] = mx;
    __syncthreads();
    if (tid == 0) {
        float bm = s_wmax[0];
#pragma unroll
        for (int w = 1; w < 8; w++) bm = fmaxf(bm, s_wmax[w]);
        atomicMax(&d_maxbits, __float_as_uint(bm));
    }
}

// ---------------- persistent Sinkhorn: one barrier/iter, no C^T -------------
#define SK_GRID 128
#define SK_DSMEM 170768

// release/acquire barrier (cooperative-groups grid-sync pattern)
__device__ __forceinline__ void batch_barrier(int batch, unsigned target) {
    __syncthreads();
    if (threadIdx.x == 0) {
        unsigned* ctr = &d_bar[batch * 32];
        asm volatile("red.release.gpu.global.add.u32 [%0], %1;"
                     :: "l"(ctr), "r"(1u) : "memory");
        unsigned v;
        do {
            asm volatile("ld.acquire.gpu.global.u32 %0, [%1];"
                         : "=r"(v) : "l"(ctr) : "memory");
        } while (v < target);
    }
    __syncthreads();
}

__device__ __forceinline__ __half2 h2u(unsigned u) { return *(__half2*)&u; }

// uint8 row dot (row as 2 uint4 per lane-chunk) vs v chunks
__device__ __forceinline__ float dotrow_q(uint4 q0, uint4 q1,
                                          const uint4 va0, const uint4 va1,
                                          const uint4 vb0, const uint4 vb1) {
    const unsigned K = 0x64006400u;
    const __half2 k = *(const __half2*)&K;
    __half2 A = __floats2half2_rn(0.f, 0.f);
    __half2 B = A;
#define QW(w, v01, v23)                                                        \
    { unsigned rlo, rhi;                                                       \
      asm("prmt.b32 %0,%1,%2,0x5140;" : "=r"(rlo) : "r"(w), "r"(0x64646464u)); \
      asm("prmt.b32 %0,%1,%2,0x7362;" : "=r"(rhi) : "r"(w), "r"(0x64646464u)); \
      A = __hfma2(__hsub2(*(__half2*)&rlo, k), *(const __half2*)&(v01), A);    \
      B = __hfma2(__hsub2(*(__half2*)&rhi, k), *(const __half2*)&(v23), B); }
    QW(q0.x, va0.x, va0.y) QW(q0.y, va0.z, va0.w)
    QW(q0.z, va1.x, va1.y) QW(q0.w, va1.z, va1.w)
    QW(q1.x, vb0.x, vb0.y) QW(q1.y, vb0.z, vb0.w)
    QW(q1.z, vb1.x, vb1.y) QW(q1.w, vb1.z, vb1.w)
#undef QW
    return __low2float(A) + __high2float(A) + __low2float(B) + __high2float(B);
}

// 4 row dots from the padded smem slab (stride 65 uint4)
__device__ __forceinline__ void dot4q_s(const uint4* __restrict__ sw,
                                        const uint4* __restrict__ sv4, int lane,
                                        float& s0, float& s1, float& s2, float& s3) {
    const uint4 va0 = sv4[2 * lane], va1 = sv4[2 * lane + 1];
    const uint4 vb0 = sv4[64 + 2 * lane], vb1 = sv4[64 + 2 * lane + 1];
    s0 = dotrow_q(sw[lane],       sw[32 + lane],  va0, va1, vb0, vb1);
    s1 = dotrow_q(sw[65 + lane],  sw[97 + lane],  va0, va1, vb0, vb1);
    s2 = dotrow_q(sw[130 + lane], sw[162 + lane], va0, va1, vb0, vb1);
    s3 = dotrow_q(sw[195 + lane], sw[227 + lane], va0, va1, vb0, vb1);
}

// fp16 4-row dot from global C
__device__ __forceinline__ void dot4h(const __half* __restrict__ rowbase,
                                      const __half2* __restrict__ sv2, int lane,
                                      float& s0, float& s1, float& s2, float& s3) {
    const uint4* r = (const uint4*)rowbase;
    __half2 z = __floats2half2_rn(0.f, 0.f);
    __half2 a0a = z, a0b = z, a1a = z, a1b = z, a2a = z, a2b = z, a3a = z, a3b = z;
#pragma unroll
    for (int k = 0; k < 4; k++) {
        int idx = lane + 32 * k;
        uint4 vv = *(const uint4*)(sv2 + idx * 4);
        __half2 v0 = h2u(vv.x), v1 = h2u(vv.y), v2 = h2u(vv.z), v3 = h2u(vv.w);
        uint4 q0 = r[idx];
        uint4 q1 = r[idx + 128];
        uint4 q2 = r[idx + 256];
        uint4 q3 = r[idx + 384];
        a0a = __hfma2(h2u(q0.x), v0, a0a); a0b = __hfma2(h2u(q0.y), v1, a0b);
        a0a = __hfma2(h2u(q0.z), v2, a0a); a0b = __hfma2(h2u(q0.w), v3, a0b);
        a1a = __hfma2(h2u(q1.x), v0, a1a); a1b = __hfma2(h2u(q1.y), v1, a1b);
        a1a = __hfma2(h2u(q1.z), v2, a1a); a1b = __hfma2(h2u(q1.w), v3, a1b);
        a2a = __hfma2(h2u(q2.x), v0, a2a); a2b = __hfma2(h2u(q2.y), v1, a2b);
        a2a = __hfma2(h2u(q2.z), v2, a2a); a2b = __hfma2(h2u(q2.w), v3, a2b);
        a3a = __hfma2(h2u(q3.x), v0, a3a); a3b = __hfma2(h2u(q3.y), v1, a3b);
        a3a = __hfma2(h2u(q3.z), v2, a3a); a3b = __hfma2(h2u(q3.w), v3, a3b);
    }
    s0 = __low2float(a0a) + __high2float(a0a) + __low2float(a0b) + __high2float(a0b);
    s1 = __low2float(a1a) + __high2float(a1a) + __low2float(a1b) + __high2float(a1b);
    s2 = __low2float(a2a) + __high2float(a2a) + __low2float(a2b) + __high2float(a2b);
    s3 = __low2float(a3a) + __high2float(a3a) + __low2float(a3b) + __high2float(a3b);
}

#define WARP_RED4(s0, s1, s2, s3)                          \
    _Pragma("unroll")                                      \
    for (int o = 16; o; o >>= 1) {                         \
        s0 += __shfl_xor_sync(0xffffffffu, s0, o);         \
        s1 += __shfl_xor_sync(0xffffffffu, s1, o);         \
        s2 += __shfl_xor_sync(0xffffffffu, s2, o);         \
        s3 += __shfl_xor_sync(0xffffffffu, s3, o);         \
    }

// decode one uint (4 uint8 cols) and accumulate into 2 half2 col-accumulators
#define CDEC(w, aE, aO, u2, kb)                                                \
    { unsigned rlo, rhi;                                                       \
      asm("prmt.b32 %0,%1,%2,0x5140;" : "=r"(rlo) : "r"(w), "r"(0x64646464u)); \
      asm("prmt.b32 %0,%1,%2,0x7362;" : "=r"(rhi) : "r"(w), "r"(0x64646464u)); \
      aE = __hfma2(__hsub2(*(__half2*)&rlo, kb), u2, aE);                      \
      aO = __hfma2(__hsub2(*(__half2*)&rhi, kb), u2, aO); }

__global__ void __launch_bounds__(1024, 1)
sinkhorn_kernel(float* __restrict__ out) {
    extern __shared__ __align__(16) unsigned char sk[];
    uint4*   slab = (uint4*)sk;
    __half*  sv   = (__half*)(sk + 133120);
    __half*  suh  = (__half*)(sk + 135168);
    __half2* sred = (__half2*)(sk + 135936);
    float*   saux = (float*)(sk + 170752);

    const int tid   = threadIdx.x;
    const int warp  = tid >> 5;
    const int lane  = tid & 31;
    const int blk   = blockIdx.x;
    const int batch = blk >> 3;
    const int rank  = blk & 7;
    const int cg    = tid >> 4;     // column group (16 cols)
    const int rc    = tid & 15;     // row chunk

    // preload uint8 slab (128 rows, padded to 65 uint4 stride)
    {
        const uint4* src = (const uint4*)(d_C8 + ((size_t)batch << 20) + ((size_t)rank << 17));
#pragma unroll
        for (int j = 0; j < 8; j++) {
            int g = tid + 1024 * j;
            slab[(g >> 6) * 65 + (g & 63)] = src[g];
        }
    }
    sv[tid] = __float2half(1.0f / NPTS);
    if (tid == 0) saux[0] = 0.0f;

    const float invM = 1.0f / __uint_as_float(d_maxbits);
    const float qsc  = invM * (2.0f / 255.0f);
    float* vp_mine = d_vpart + (batch * 8 + rank) * NPTS;
    const float* vp_all = d_vpart + batch * 8 * NPTS;
    const unsigned KB = 0x64006400u;
    const __half2 kb = *(const __half2*)&KB;
    __syncthreads();

    unsigned step = 0;
    for (int iter = 0; iter < INT8_IT; iter++) {
        // ---- u (local rows, smem slab)
        float s0, s1, s2, s3;
        dot4q_s(slab + warp * 4 * 65, (const uint4*)sv, lane, s0, s1, s2, s3);
        WARP_RED4(s0, s1, s2, s3)
        if (lane < 4) {
            float s = (lane == 0) ? s0 : (lane == 1) ? s1 : (lane == 2) ? s2 : s3;
            float uv = 1.0f / (fmaf(qsc, s, EPS_SK));
            suh[warp * 4 + lane] = __float2half(uv);
        }
        __syncthreads();

        // ---- column partials from own slab (rows rc+16j, bank-safe)
        {
            __half2 z = __floats2half2_rn(0.f, 0.f);
            __half2 acc[8] = {z, z, z, z, z, z, z, z};
#pragma unroll
            for (int j = 0; j < 8; j++) {
                int r = rc + 16 * j;
                uint4 q = slab[r * 65 + cg];
                __half2 u2 = __half2half2(suh[r]);
                CDEC(q.x, acc[0], acc[1], u2, kb)
                CDEC(q.y, acc[2], acc[3], u2, kb)
                CDEC(q.z, acc[4], acc[5], u2, kb)
                CDEC(q.w, acc[6], acc[7], u2, kb)
            }
#pragma unroll
            for (int h = 0; h < 8; h++) sred[(cg * 8 + h) * 17 + rc] = acc[h];
        }
        __syncthreads();
        if (tid < 512) {
            const __half2* p = sred + tid * 17;
            float fx = 0.f, fy = 0.f;
#pragma unroll
            for (int k2 = 0; k2 < 16; k2++) {
                float2 f = __half22float2(p[k2]);
                fx += f.x; fy += f.y;
            }
            int m0 = 16 * (tid >> 3) + 2 * (tid & 7);
            float2 st; st.x = fx; st.y = fy;
            *(float2*)(vp_mine + m0) = st;
        }
        batch_barrier(batch, 8 * (++step));
        // ---- v recompute (identical in all blocks of the batch)
        {
            float a = 0.f;
#pragma unroll
            for (int k = 0; k < 8; k++) a += vp_all[k * NPTS + tid];
            sv[tid] = __float2half(1.0f / (fmaf(qsc, a, EPS_SK)));
        }
        __syncthreads();
    }

    // ---- polish iteration(s): same structure on fp16 C from global
    const __half* Cb = d_C + ((size_t)batch << 20) + ((size_t)rank << 17);
    float last_a = 0.0f;   // this thread's final column-sum (C^T u)_tid
    for (int iter = 0; iter < POLISH_IT; iter++) {
        float s0, s1, s2, s3;
        dot4h(Cb + (size_t)(warp * 4) * NPTS, (const __half2*)sv, lane, s0, s1, s2, s3);
        WARP_RED4(s0, s1, s2, s3)
        if (lane < 4) {
            float s = (lane == 0) ? s0 : (lane == 1) ? s1 : (lane == 2) ? s2 : s3;
            float uv = 1.0f / (fmaf(invM, s, EPS_SK));
            suh[warp * 4 + lane] = __float2half(uv);
        }
        __syncthreads();
        {
            __half2 z = __floats2half2_rn(0.f, 0.f);
            __half2 acc[8] = {z, z, z, z, z, z, z, z};
#pragma unroll
            for (int j = 0; j < 8; j++) {
                int r = rc + 16 * j;
                const uint4* gq = (const uint4*)(Cb + (size_t)r * NPTS) + 2 * cg;
                uint4 q0 = gq[0], q1 = gq[1];
                __half2 u2 = __half2half2(suh[r]);
                acc[0] = __hfma2(h2u(q0.x), u2, acc[0]);
                acc[1] = __hfma2(h2u(q0.y), u2, acc[1]);
                acc[2] = __hfma2(h2u(q0.z), u2, acc[2]);
                acc[3] = __hfma2(h2u(q0.w), u2, acc[3]);
                acc[4] = __hfma2(h2u(q1.x), u2, acc[4]);
                acc[5] = __hfma2(h2u(q1.y), u2, acc[5]);
                acc[6] = __hfma2(h2u(q1.z), u2, acc[6]);
                acc[7] = __hfma2(h2u(q1.w), u2, acc[7]);
            }
#pragma unroll
            for (int h = 0; h < 8; h++) sred[(cg * 8 + h) * 17 + rc] = acc[h];
        }
        __syncthreads();
        if (tid < 512) {
            const __half2* p = sred + tid * 17;
            float fx = 0.f, fy = 0.f;
#pragma unroll
            for (int k2 = 0; k2 < 16; k2++) {
                float2 f = __half22float2(p[k2]);
                fx += f.x; fy += f.y;
            }
            int m0 = 16 * (tid >> 3) + 2 * (tid & 7);
            float2 st; st.x = fx; st.y = fy;
            *(float2*)(vp_mine + m0) = st;
        }
        batch_barrier(batch, 8 * (++step));
        {
            float a = 0.f;
#pragma unroll
            for (int k = 0; k < 8; k++) a += vp_all[k * NPTS + tid];
            last_a = a;
            sv[tid] = __float2half(1.0f / (fmaf(invM, a, EPS_SK)));
        }
        __syncthreads();
    }

    // ---- distance = invM * Σ_j a_j v_j  (stationarity-fused final reduction)
    {
        float v  = 1.0f / (fmaf(invM, last_a, EPS_SK));
        float c  = invM * last_a * v;
#pragma unroll
        for (int o = 16; o; o >>= 1) c += __shfl_xor_sync(0xffffffffu, c, o);
        if (lane == 0) atomicAdd(&saux[0], c);
        __syncthreads();
        if (tid == 0 && rank == 0) atomicAdd(out, saux[0] * (1.0f / BATCHES));
    }
}

// ---------------- launch ----------------------------------------------------
extern "C" void kernel_launch(void* const* d_in, const int* in_sizes, int n_in,
                              void* d_out, int out_size) {
    (void)in_sizes; (void)n_in; (void)out_size;
    const float* x = (const float*)d_in[0];
    const float* y = (const float*)d_in[1];
    float* out = (float*)d_out;

    static int attr_set = 0;
    if (!attr_set) {
        cudaFuncSetAttribute(sinkhorn_kernel,
                             cudaFuncAttributeMaxDynamicSharedMemorySize, SK_DSMEM);
        cudaFuncSetAttribute(gemm_cost_mma,
                             cudaFuncAttributeMaxDynamicSharedMemorySize, GEMM_DSMEM);
        attr_set = 1;
    }

    normc_kernel<<<4096, 256>>>(x, y, out);
    dim3 g(8, 8, 16);
    gemm_cost_mma<<<g, 256, GEMM_DSMEM>>>();
    sinkhorn_kernel<<<SK_GRID, 1024, SK_DSMEM>>>(out);
}

// round 17
// speedup vs baseline: 2.4995x; 1.0797x over previous
#include <cuda_runtime.h>
#include <cuda_fp16.h>
#include <cstdint>

#define BATCHES 16
#define NPTS    1024
#define DIMS    1024
#define EPS_SK  1e-3f
#define POLISH_IT  2

// ---------------- scratch (static device globals; no runtime alloc) --------
__device__ __half  d_C [BATCHES * NPTS * NPTS];          // fp16 C (32 MB)
__device__ __half  d_xh[BATCHES * NPTS * DIMS];
__device__ __half  d_yh[BATCHES * NPTS * DIMS];
__device__ float   d_vpart[BATCHES * 8 * NPTS];          // per-rank column partials
__device__ unsigned d_maxbits;
__device__ unsigned d_bar[BATCHES * 32];                 // per-batch barrier ctrs

// ---------------- normalize rows -> fp16 (+ fused per-replay init) ----------
__global__ void normc_kernel(const float* __restrict__ x,
                             const float* __restrict__ y,
                             float* __restrict__ out) {
    if (blockIdx.x == 0) {
        for (int t = threadIdx.x; t < BATCHES * 32; t += blockDim.x) d_bar[t] = 0u;
        if (threadIdx.x == 0) { d_maxbits = 0u; out[0] = 0.0f; }
    }
    int gw   = blockIdx.x * 8 + (threadIdx.x >> 5);
    int lane = threadIdx.x & 31;
    const float* src;
    __half* dst;
    if (gw < BATCHES * NPTS) { src = x + (size_t)gw * DIMS;                     dst = d_xh + (size_t)gw * DIMS; }
    else                     { src = y + (size_t)(gw - BATCHES * NPTS) * DIMS;  dst = d_yh + (size_t)(gw - BATCHES * NPTS) * DIMS; }
    const float4* p = (const float4*)src;
    float4 f[8];
    float ss = 0.0f;
#pragma unroll
    for (int k = 0; k < 8; k++) {
        f[k] = p[lane + 32 * k];
        ss += f[k].x * f[k].x + f[k].y * f[k].y + f[k].z * f[k].z + f[k].w * f[k].w;
    }
#pragma unroll
    for (int o = 16; o; o >>= 1) ss += __shfl_xor_sync(0xffffffffu, ss, o);
    float inv = 1.0f / fmaxf(sqrtf(ss), 1e-12f);
#pragma unroll
    for (int k = 0; k < 8; k++) {
        __half2 h0 = __floats2half2_rn(f[k].x * inv, f[k].y * inv);
        __half2 h1 = __floats2half2_rn(f[k].z * inv, f[k].w * inv);
        uint2 u; u.x = *(unsigned*)&h0; u.y = *(unsigned*)&h1;
        *(uint2*)(dst + (size_t)(lane + 32 * k) * 4) = u;
    }
}

// ---------------- tensor-core cost GEMM (3-stage cp.async pipeline) ---------
#define SSTRIDE 40
#define CTSTR   136
#define GEMM_STG_B (128 * SSTRIDE * 2)            // 10240 B per stage buffer
#define GEMM_DSMEM (6 * GEMM_STG_B)               // 3 stages x (A,B) = 61440 B

#define CP_ASYNC16(saddr, gptr) \
    asm volatile("cp.async.cg.shared.global [%0], [%1], 16;" :: "r"(saddr), "l"(gptr))
#define CP_COMMIT() asm volatile("cp.async.commit_group;")
#define CP_WAIT0()  asm volatile("cp.async.wait_group 0;" ::: "memory")
#define CP_WAIT1()  asm volatile("cp.async.wait_group 1;" ::: "memory")

#define LDSM_X4(r0, r1, r2, r3, addr)                                          \
    asm volatile("ldmatrix.sync.aligned.m8n8.x4.shared.b16 {%0,%1,%2,%3}, [%4];" \
        : "=r"(r0), "=r"(r1), "=r"(r2), "=r"(r3) : "r"(addr))

__device__ __forceinline__ void mma16816(float* d, const unsigned* a, const unsigned* b) {
    asm volatile(
        "mma.sync.aligned.m16n8k16.row.col.f32.f16.f16.f32 "
        "{%0,%1,%2,%3}, {%4,%5,%6,%7}, {%8,%9}, {%0,%1,%2,%3};"
        : "+f"(d[0]), "+f"(d[1]), "+f"(d[2]), "+f"(d[3])
        : "r"(a[0]), "r"(a[1]), "r"(a[2]), "r"(a[3]), "r"(b[0]), "r"(b[1]));
}

__global__ void __launch_bounds__(256, 2)
gemm_cost_mma(void) {
    extern __shared__ __align__(16) __half gsm[];   // 3-stage staging / epilogue Ct
    __shared__ float s_wmax[8];

    const int tid  = threadIdx.x;
    const int warp = tid >> 5;
    const int lane = tid & 31;
    const int wm   = warp >> 2;
    const int wn   = warp & 3;
    const int lq   = lane >> 2;
    const int lr4  = lane & 3;
    const int bz   = blockIdx.z;
    const int n0   = blockIdx.y * 128;
    const int m0   = blockIdx.x * 128;

    const __half* xb = d_xh + ((size_t)bz << 20);
    const __half* yb = d_yh + ((size_t)bz << 20);

    const int lrow = tid >> 2;
    const int lseg = tid & 3;
    const __half* gxa = xb + (size_t)(n0 + lrow) * DIMS + lseg * 8;
    const __half* gxb = xb + (size_t)(n0 + lrow + 64) * DIMS + lseg * 8;
    const __half* gya = yb + (size_t)(m0 + lrow) * DIMS + lseg * 8;
    const __half* gyb = yb + (size_t)(m0 + lrow + 64) * DIMS + lseg * 8;

    const uint32_t smem_u32 = (uint32_t)__cvta_generic_to_shared(gsm);
    const uint32_t STG = (uint32_t)GEMM_STG_B;
    const uint32_t BBASE = 3u * STG;
    const uint32_t sAa = smem_u32 + 2u * (lrow * SSTRIDE + lseg * 8);
    const uint32_t sAb = smem_u32 + 2u * ((lrow + 64) * SSTRIDE + lseg * 8);
    const uint32_t sBa = smem_u32 + BBASE + 2u * (lrow * SSTRIDE + lseg * 8);
    const uint32_t sBb = smem_u32 + BBASE + 2u * ((lrow + 64) * SSTRIDE + lseg * 8);

#define LOAD_STAGE(stg, k0)                                   \
    { CP_ASYNC16(sAa + (stg) * STG, gxa + (k0));              \
      CP_ASYNC16(sAb + (stg) * STG, gxb + (k0));              \
      CP_ASYNC16(sBa + (stg) * STG, gya + (k0));              \
      CP_ASYNC16(sBb + (stg) * STG, gyb + (k0));              \
      CP_COMMIT(); }

    const int arow_l = (lane & 7) + ((lane >> 3) & 1) * 8;
    const int acol_l = (lane >> 4) * 8;
    const int brow_l = lane & 7;
    const int bcol_l = ((lane >> 3) & 1) * 8;
    const int bjoff_l = (lane >> 4) * 8;     // x4 B: lanes 16-31 -> next j-tile

    float acc[4][4][4];
#pragma unroll
    for (int i = 0; i < 4; i++)
#pragma unroll
        for (int j = 0; j < 4; j++)
#pragma unroll
            for (int q = 0; q < 4; q++) acc[i][j][q] = 0.0f;

    LOAD_STAGE(0u, 0);
    LOAD_STAGE(1u, 32);

    unsigned stg = 0;
    for (int it = 0; it < 32; it++) {
        if (it < 31) CP_WAIT1(); else CP_WAIT0();
        __syncthreads();
        if (it < 30) {
            unsigned nstg = stg + 2; if (nstg >= 3) nstg -= 3;
            LOAD_STAGE(nstg, (it + 2) * 32);
        }
        const uint32_t aS = smem_u32 + stg * STG;
        const uint32_t bS = smem_u32 + BBASE + stg * STG;
#pragma unroll
        for (int ks = 0; ks < 32; ks += 16) {
            unsigned a[4][4], b[4][2];
#pragma unroll
            for (int i = 0; i < 4; i++) {
                uint32_t ad = aS + 2u * ((wm * 64 + i * 16 + arow_l) * SSTRIDE + ks + acol_l);
                LDSM_X4(a[i][0], a[i][1], a[i][2], a[i][3], ad);
            }
#pragma unroll
            for (int j = 0; j < 4; j += 2) {
                uint32_t bd = bS + 2u * ((wn * 32 + j * 8 + bjoff_l + brow_l) * SSTRIDE + ks + bcol_l);
                LDSM_X4(b[j][0], b[j][1], b[j + 1][0], b[j + 1][1], bd);
            }
#pragma unroll
            for (int i = 0; i < 4; i++)
#pragma unroll
                for (int j = 0; j < 4; j++) mma16816(acc[i][j], a[i], b[j]);
        }
        stg = (stg == 2) ? 0u : stg + 1u;
    }
    __syncthreads();
#undef LOAD_STAGE

    // epilogue: cost = 1 - dot; stage fp16 tile, write C fp16
    __half* Ct = gsm;
    float mx = 0.0f;
#pragma unroll
    for (int i = 0; i < 4; i++) {
        const int r0 = wm * 64 + i * 16 + lq;
#pragma unroll
        for (int j = 0; j < 4; j++) {
            const int c = wn * 32 + j * 8 + lr4 * 2;
            float c00 = 1.0f - acc[i][j][0];
            float c01 = 1.0f - acc[i][j][1];
            float c10 = 1.0f - acc[i][j][2];
            float c11 = 1.0f - acc[i][j][3];
            mx = fmaxf(mx, fmaxf(fmaxf(c00, c01), fmaxf(c10, c11)));
            *(__half2*)(Ct + r0 * CTSTR + c)       = __floats2half2_rn(c00, c01);
            *(__half2*)(Ct + (r0 + 8) * CTSTR + c) = __floats2half2_rn(c10, c11);
        }
    }
    __syncthreads();

    const size_t base = (size_t)bz << 20;
    const int row = tid >> 1;
    const int off = (tid & 1) * 64;
#pragma unroll
    for (int u = 0; u < 8; u++) {
        uint4 q = *(const uint4*)(Ct + row * CTSTR + off + u * 8);
        *(uint4*)(d_C + base + (size_t)(n0 + row) * NPTS + m0 + off + u * 8) = q;
    }

#pragma unroll
    for (int o = 16; o; o >>= 1) mx = fmaxf(mx, __shfl_xor_sync(0xffffffffu, mx, o));
    if (lane == 0) s_wmax[warp] = mx;
    __syncthreads();
    if (tid == 0) {
        float bm = s_wmax[0];
#pragma unroll
        for (int w = 1; w < 8; w++) bm = fmaxf(bm, s_wmax[w]);
        atomicMax(&d_maxbits, __float_as_uint(bm));
    }
}

// ---------------- persistent Sinkhorn: fp16-only, one barrier/iter ----------
#define SK_GRID 128
// smem: sv 0..2048 | suh 2048..2304 | sred 2304..37120 | saux 37120..37136
#define SK_DSMEM 37136

__device__ __forceinline__ void batch_barrier(int batch, unsigned target) {
    __syncthreads();
    if (threadIdx.x == 0) {
        unsigned* ctr = &d_bar[batch * 32];
        asm volatile("red.release.gpu.global.add.u32 [%0], %1;"
                     :: "l"(ctr), "r"(1u) : "memory");
        unsigned v;
        do {
            asm volatile("ld.acquire.gpu.global.u32 %0, [%1];"
                         : "=r"(v) : "l"(ctr) : "memory");
        } while (v < target);
    }
    __syncthreads();
}

__device__ __forceinline__ __half2 h2u(unsigned u) { return *(__half2*)&u; }

// fp16 4-row dot from global C
__device__ __forceinline__ void dot4h(const __half* __restrict__ rowbase,
                                      const __half2* __restrict__ sv2, int lane,
                                      float& s0, float& s1, float& s2, float& s3) {
    const uint4* r = (const uint4*)rowbase;
    __half2 z = __floats2half2_rn(0.f, 0.f);
    __half2 a0a = z, a0b = z, a1a = z, a1b = z, a2a = z, a2b = z, a3a = z, a3b = z;
#pragma unroll
    for (int k = 0; k < 4; k++) {
        int idx = lane + 32 * k;
        uint4 vv = *(const uint4*)(sv2 + idx * 4);
        __half2 v0 = h2u(vv.x), v1 = h2u(vv.y), v2 = h2u(vv.z), v3 = h2u(vv.w);
        uint4 q0 = r[idx];
        uint4 q1 = r[idx + 128];
        uint4 q2 = r[idx + 256];
        uint4 q3 = r[idx + 384];
        a0a = __hfma2(h2u(q0.x), v0, a0a); a0b = __hfma2(h2u(q0.y), v1, a0b);
        a0a = __hfma2(h2u(q0.z), v2, a0a); a0b = __hfma2(h2u(q0.w), v3, a0b);
        a1a = __hfma2(h2u(q1.x), v0, a1a); a1b = __hfma2(h2u(q1.y), v1, a1b);
        a1a = __hfma2(h2u(q1.z), v2, a1a); a1b = __hfma2(h2u(q1.w), v3, a1b);
        a2a = __hfma2(h2u(q2.x), v0, a2a); a2b = __hfma2(h2u(q2.y), v1, a2b);
        a2a = __hfma2(h2u(q2.z), v2, a2a); a2b = __hfma2(h2u(q2.w), v3, a2b);
        a3a = __hfma2(h2u(q3.x), v0, a3a); a3b = __hfma2(h2u(q3.y), v1, a3b);
        a3a = __hfma2(h2u(q3.z), v2, a3a); a3b = __hfma2(h2u(q3.w), v3, a3b);
    }
    s0 = __low2float(a0a) + __high2float(a0a) + __low2float(a0b) + __high2float(a0b);
    s1 = __low2float(a1a) + __high2float(a1a) + __low2float(a1b) + __high2float(a1b);
    s2 = __low2float(a2a) + __high2float(a2a) + __low2float(a2b) + __high2float(a2b);
    s3 = __low2float(a3a) + __high2float(a3a) + __low2float(a3b) + __high2float(a3b);
}

#define WARP_RED4(s0, s1, s2, s3)                          \
    _Pragma("unroll")                                      \
    for (int o = 16; o; o >>= 1) {                         \
        s0 += __shfl_xor_sync(0xffffffffu, s0, o);         \
        s1 += __shfl_xor_sync(0xffffffffu, s1, o);         \
        s2 += __shfl_xor_sync(0xffffffffu, s2, o);         \
        s3 += __shfl_xor_sync(0xffffffffu, s3, o);         \
    }

__global__ void __launch_bounds__(1024, 1)
sinkhorn_kernel(float* __restrict__ out) {
    extern __shared__ __align__(16) unsigned char sk[];
    __half*  sv   = (__half*)(sk);
    __half*  suh  = (__half*)(sk + 2048);
    __half2* sred = (__half2*)(sk + 2304);
    float*   saux = (float*)(sk + 37120);

    const int tid   = threadIdx.x;
    const int warp  = tid >> 5;
    const int lane  = tid & 31;
    const int blk   = blockIdx.x;
    const int batch = blk >> 3;
    const int rank  = blk & 7;
    const int cg    = tid >> 4;     // column group (16 cols)
    const int rc    = tid & 15;     // row chunk

    sv[tid] = __float2half(1.0f / NPTS);
    if (tid == 0) saux[0] = 0.0f;

    const float invM = 1.0f / __uint_as_float(d_maxbits);
    float* vp_mine = d_vpart + (batch * 8 + rank) * NPTS;
    const float* vp_all = d_vpart + batch * 8 * NPTS;
    const __half* Cb = d_C + ((size_t)batch << 20) + ((size_t)rank << 17);
    __syncthreads();

    unsigned step = 0;
    float last_a = 0.0f;   // this thread's final column-sum (C^T u)_tid
    for (int iter = 0; iter < POLISH_IT; iter++) {
        // ---- u = 1 / (invM * (C v) + eps)   (block's 128 local rows)
        float s0, s1, s2, s3;
        dot4h(Cb + (size_t)(warp * 4) * NPTS, (const __half2*)sv, lane, s0, s1, s2, s3);
        WARP_RED4(s0, s1, s2, s3)
        if (lane < 4) {
            float s = (lane == 0) ? s0 : (lane == 1) ? s1 : (lane == 2) ? s2 : s3;
            float uv = 1.0f / (fmaf(invM, s, EPS_SK));
            suh[warp * 4 + lane] = __float2half(uv);
        }
        __syncthreads();
        // ---- column partials a_j += C[r][j] * u[r] over local rows
        {
            __half2 z = __floats2half2_rn(0.f, 0.f);
            __half2 acc[8] = {z, z, z, z, z, z, z, z};
#pragma unroll
            for (int j = 0; j < 8; j++) {
                int r = rc + 16 * j;
                const uint4* gq = (const uint4*)(Cb + (size_t)r * NPTS) + 2 * cg;
                uint4 q0 = gq[0], q1 = gq[1];
                __half2 u2 = __half2half2(suh[r]);
                acc[0] = __hfma2(h2u(q0.x), u2, acc[0]);
                acc[1] = __hfma2(h2u(q0.y), u2, acc[1]);
                acc[2] = __hfma2(h2u(q0.z), u2, acc[2]);
                acc[3] = __hfma2(h2u(q0.w), u2, acc[3]);
                acc[4] = __hfma2(h2u(q1.x), u2, acc[4]);
                acc[5] = __hfma2(h2u(q1.y), u2, acc[5]);
                acc[6] = __hfma2(h2u(q1.z), u2, acc[6]);
                acc[7] = __hfma2(h2u(q1.w), u2, acc[7]);
            }
#pragma unroll
            for (int h = 0; h < 8; h++) sred[(cg * 8 + h) * 17 + rc] = acc[h];
        }
        __syncthreads();
        if (tid < 512) {
            const __half2* p = sred + tid * 17;
            float fx = 0.f, fy = 0.f;
#pragma unroll
            for (int k2 = 0; k2 < 16; k2++) {
                float2 f = __half22float2(p[k2]);
                fx += f.x; fy += f.y;
            }
            int m0 = 16 * (tid >> 3) + 2 * (tid & 7);
            float2 st; st.x = fx; st.y = fy;
            *(float2*)(vp_mine + m0) = st;
        }
        batch_barrier(batch, 8 * (++step));
        // ---- v recompute (identical in all blocks of the batch)
        {
            float a = 0.f;
#pragma unroll
            for (int k = 0; k < 8; k++) a += vp_all[k * NPTS + tid];
            last_a = a;
            sv[tid] = __float2half(1.0f / (fmaf(invM, a, EPS_SK)));
        }
        __syncthreads();
    }

    // ---- distance = invM * Σ_j a_j v_j  (stationarity-fused final reduction)
    {
        float v  = 1.0f / (fmaf(invM, last_a, EPS_SK));
        float c  = invM * last_a * v;
#pragma unroll
        for (int o = 16; o; o >>= 1) c += __shfl_xor_sync(0xffffffffu, c, o);
        if (lane == 0) atomicAdd(&saux[0], c);
        __syncthreads();
        if (tid == 0 && rank == 0) atomicAdd(out, saux[0] * (1.0f / BATCHES));
    }
}

// ---------------- launch ----------------------------------------------------
extern "C" void kernel_launch(void* const* d_in, const int* in_sizes, int n_in,
                              void* d_out, int out_size) {
    (void)in_sizes; (void)n_in; (void)out_size;
    const float* x = (const float*)d_in[0];
    const float* y = (const float*)d_in[1];
    float* out = (float*)d_out;

    static int attr_set = 0;
    if (!attr_set) {
        cudaFuncSetAttribute(sinkhorn_kernel,
                             cudaFuncAttributeMaxDynamicSharedMemorySize, SK_DSMEM);
        cudaFuncSetAttribute(gemm_cost_mma,
                             cudaFuncAttributeMaxDynamicSharedMemorySize, GEMM_DSMEM);
        attr_set = 1;
    }

    normc_kernel<<<4096, 256>>>(x, y, out);
    dim3 g(8, 8, 16);
    gemm_cost_mma<<<g, 256, GEMM_DSMEM>>>();
    sinkhorn_kernel<<<SK_GRID, 1024, SK_DSMEM>>>(out);
}